// round 9
// baseline (speedup 1.0000x reference)
#include <cuda_runtime.h>
#include <math.h>
#include <stdint.h>

#define V_   1000
#define H_   512
#define D_   512
#define NH   8
#define DK   64
#define MEM_ 512
#define BS   128
#define TMAX 160
#define NBLK 128
#define NFC  125            // fc tiles of 8 outputs: 125*8 = 1000

#define OUT_H_OFF (TMAX*BS*V_)                 // 20,480,000
#define OUT_S_OFF (OUT_H_OFF + TMAX*BS*H_)     // 30,965,760

// dynamic smem layout (bytes)
// [0, 44032)        : per-phase overlays (QSm / GruSm / FcSm / attention arrays)
// [44032, 44064)    : 4 mbarriers
// [44160, 175232)   : 4 x 32KB TMA ring buffers
#define OFF_QS     0
#define OFF_SC     2048
#define OFF_RED    18432
#define OFF_WRED   34816
#define OFF_WRED2  34880
#define OFF_INVS   34944
#define OFF_MBAR   44032
#define OFF_BUF    44160
#define CHUNK_B    32768
#define SMEM_TOTAL (OFF_BUF + 4*CHUNK_B)      // 175232

// ---------------- device scratch (static; no allocations) ----------------
__device__ float g_kt[(size_t)BS*NH*DK*MEM_];  // K transposed: [b][h][d][m]
__device__ float g_vp[(size_t)BS*NH*MEM_*DK];  // V: [b][h][m][d]
__device__ float g_h2[2][BS*H_];               // double-buffered hidden
__device__ float g_q [BS*D_];
__device__ float g_ctx[BS*D_];
__device__ float g_pv[NFC*BS];                 // fc partial argmax values
__device__ int   g_pi[NFC*BS];                 // fc partial argmax indices
__device__ unsigned g_bar_count;
__device__ volatile unsigned g_bar_gen;

// ---------------- PTX helpers ----------------
__device__ __forceinline__ unsigned s2u(const void* p) {
    return (unsigned)__cvta_generic_to_shared(p);
}
__device__ __forceinline__ void mbar_init(unsigned a, unsigned cnt) {
    asm volatile("mbarrier.init.shared.b64 [%0], %1;" :: "r"(a), "r"(cnt) : "memory");
}
__device__ __forceinline__ void mbar_expect_tx(unsigned a, unsigned bytes) {
    asm volatile("mbarrier.arrive.expect_tx.shared.b64 _, [%0], %1;"
                 :: "r"(a), "r"(bytes) : "memory");
}
__device__ __forceinline__ void mbar_wait(unsigned a, unsigned parity) {
    unsigned done;
    asm volatile(
        "{\n\t.reg .pred p;\n\t"
        "mbarrier.try_wait.parity.acquire.cta.shared::cta.b64 p, [%1], %2, 0x989680;\n\t"
        "selp.b32 %0, 1, 0, p;\n\t}"
        : "=r"(done) : "r"(a), "r"(parity) : "memory");
    while (!done) {
        asm volatile(
            "{\n\t.reg .pred p;\n\t"
            "mbarrier.try_wait.parity.acquire.cta.shared::cta.b64 p, [%1], %2, 0x989680;\n\t"
            "selp.b32 %0, 1, 0, p;\n\t}"
            : "=r"(done) : "r"(a), "r"(parity) : "memory");
    }
}
__device__ __forceinline__ void tma_g2s(unsigned dst, const void* src, unsigned bytes, unsigned mbar) {
    asm volatile(
        "cp.async.bulk.shared::cluster.global.mbarrier::complete_tx::bytes [%0], [%1], %2, [%3];"
        :: "r"(dst), "l"(src), "r"(bytes), "r"(mbar) : "memory");
}
__device__ __forceinline__ float sigmoidf_(float x) { return 1.f / (1.f + expf(-x)); }

// ---------------- init ----------------
__global__ void init_kernel() {
    int i = blockIdx.x * blockDim.x + threadIdx.x;
    int total = 2 * BS * H_;
    for (; i < total; i += gridDim.x * blockDim.x)
        ((float*)g_h2)[i] = 0.f;
}

// ---------------- KV projection (once). K written transposed. ----------------
__global__ void __launch_bounds__(256) kvproj_kernel(
    const float* __restrict__ memory, const float* __restrict__ Wk, const float* __restrict__ bk,
    const float* __restrict__ Wv, const float* __restrict__ bv)
{
    __shared__ float Xs[64][17];
    __shared__ float Ks[64][17];
    __shared__ float Vs[64][17];
    int m0 = blockIdx.x * 64, n0 = blockIdx.y * 64, b = blockIdx.z;
    int tid = threadIdx.x;
    int tn = tid & 15, tm = tid >> 4;
    float accK[4][4] = {}, accV[4][4] = {};

    for (int k0 = 0; k0 < D_; k0 += 16) {
        #pragma unroll
        for (int i = 0; i < 4; i++) {
            int e = tid + i * 256;
            int kk = e & 15, mm = e >> 4;
            Xs[mm][kk] = memory[((size_t)(m0 + mm) * BS + b) * D_ + k0 + kk];
            Ks[mm][kk] = Wk[(size_t)(n0 + mm) * D_ + k0 + kk];
            Vs[mm][kk] = Wv[(size_t)(n0 + mm) * D_ + k0 + kk];
        }
        __syncthreads();
        #pragma unroll
        for (int kk = 0; kk < 16; kk++) {
            float xv[4], kw[4], vw[4];
            #pragma unroll
            for (int i = 0; i < 4; i++) xv[i] = Xs[tm * 4 + i][kk];
            #pragma unroll
            for (int j = 0; j < 4; j++) { kw[j] = Ks[tn * 4 + j][kk]; vw[j] = Vs[tn * 4 + j][kk]; }
            #pragma unroll
            for (int i = 0; i < 4; i++)
                #pragma unroll
                for (int j = 0; j < 4; j++) {
                    accK[i][j] = fmaf(xv[i], kw[j], accK[i][j]);
                    accV[i][j] = fmaf(xv[i], vw[j], accV[i][j]);
                }
        }
        __syncthreads();
    }
    #pragma unroll
    for (int i = 0; i < 4; i++) {
        int m = m0 + tm * 4 + i;
        #pragma unroll
        for (int j = 0; j < 4; j++) {
            int n = n0 + tn * 4 + j;
            int h = n >> 6, d = n & 63;
            g_kt[(((size_t)b * NH + h) * DK + d) * MEM_ + m]  = accK[i][j] + bk[n];
            g_vp[(((size_t)b * NH + h) * MEM_ + m) * DK + d]  = accV[i][j] + bv[n];
        }
    }
}

// ---------------- phase overlays ----------------
struct QSm  { float Xs[32][133]; float Ws[4][33]; int toks[BS]; };
struct GruSm{ float Xs[2][32][133]; float Ws[2][12][33]; float red[4][64][6]; };
struct FcSm { float Xs[32][133]; float Ws[8][33]; float apv[4][BS]; int api[4][BS]; };

extern __shared__ __align__(128) unsigned char dynsm[];

__device__ __forceinline__ void grid_bar() {
    __syncthreads();
    if (threadIdx.x == 0) {
        unsigned gen = g_bar_gen;
        __threadfence();
        unsigned ticket = atomicAdd(&g_bar_count, 1u);
        if (ticket == gridDim.x - 1) {
            g_bar_count = 0;
            __threadfence();
            g_bar_gen = gen + 1;
        } else {
            while (g_bar_gen == gen) __nanosleep(32);
            __threadfence();
        }
    }
    __syncthreads();
}

// ---------------- persistent decode kernel (whole 160-step loop) ----------------
__global__ void __launch_bounds__(512, 1) decode_kernel(
    const float* __restrict__ emb,  const float* __restrict__ Wq,  const float* __restrict__ bq,
    const float* __restrict__ Wih,  const float* __restrict__ Whh,
    const float* __restrict__ bih,  const float* __restrict__ bhh,
    const float* __restrict__ Wfc,  const float* __restrict__ bfc,
    const int*   __restrict__ lens, float* __restrict__ out)
{
    const int bid = blockIdx.x;
    const int tid = threadIdx.x;

    // attention smem views
    float* qs           = (float*)(dynsm + OFF_QS);
    float (*sc)[MEM_]   = (float(*)[MEM_])(dynsm + OFF_SC);
    float (*red)[8][DK] = (float(*)[8][DK])(dynsm + OFF_RED);
    float* wred  = (float*)(dynsm + OFF_WRED);
    float* wred2 = (float*)(dynsm + OFF_WRED2);
    float* invs  = (float*)(dynsm + OFF_INVS);
    const unsigned mbar0 = s2u(dynsm + OFF_MBAR);
    const unsigned buf_s = s2u(dynsm + OFF_BUF);
    float* bufs = (float*)(dynsm + OFF_BUF);

    if (tid == 0)
        for (int j = 0; j < 4; j++) mbar_init(mbar0 + 8u * j, 1u);
    __syncthreads();

    for (int t = 0; t < TMAX; t++) {
        const float* hcur = g_h2[t & 1];
        float* hnext = g_h2[(t + 1) & 1];

        // ================= phase Q: toks + q = [emb[tok],h] @ Wq^T + bq =========
        {
            QSm& S = *(QSm*)dynsm;
            if (tid < BS) {
                int b = tid, bi = 0;
                if (t > 0) {
                    float bv = -3.4e38f;
                    for (int p = 0; p < NFC; p++) {
                        float v = g_pv[p * BS + b];
                        if (v > bv) { bv = v; bi = g_pi[p * BS + b]; }
                    }
                }
                S.toks[b] = bi;
            }
            __syncthreads();
            const int n = bid * 4 + (tid >> 7);
            const int b = tid & 127;
            float acc = 0.f;
            for (int k0 = 0; k0 < 2 * H_; k0 += 32) {
                #pragma unroll
                for (int i = 0; i < 8; i++) {
                    int e = tid + i * 512;
                    int kk = e & 31, bb = e >> 5;
                    int j = k0 + kk;
                    S.Xs[kk][bb] = (j < H_) ? emb[(size_t)S.toks[bb] * H_ + j]
                                            : hcur[bb * H_ + (j - H_)];
                }
                if (tid < 128) {
                    int row = tid >> 5, kk = tid & 31;
                    S.Ws[row][kk] = Wq[(size_t)(bid * 4 + row) * (2 * H_) + k0 + kk];
                }
                __syncthreads();
                const float* wr = S.Ws[tid >> 7];
                #pragma unroll
                for (int kk = 0; kk < 32; kk++)
                    acc = fmaf(S.Xs[kk][b], wr[kk], acc);
                __syncthreads();
            }
            g_q[b * D_ + n] = acc + bq[n];
        }
        grid_bar();

        // ================= phase ATT: block = batch; TMA-pipelined K then V =====
        {
            qs[tid] = g_q[bid * D_ + tid];
            __syncthreads();   // qs visible; all smem reads of prior phase retired

            // ---- K phase: 32 chunks of [16 d][512 m] (32 KB each) ----
            const float* ksrc = g_kt + (size_t)bid * NH * DK * MEM_;
            if (tid == 0) {
                #pragma unroll
                for (int j = 0; j < 3; j++) {
                    mbar_expect_tx(mbar0 + 8u * j, CHUNK_B);
                    tma_g2s(buf_s + j * CHUNK_B, ksrc + (size_t)j * 8192, CHUNK_B, mbar0 + 8u * j);
                }
            }
            float acc = 0.f;
            for (int c = 0; c < 32; c++) {
                if (tid == 0 && c + 3 < 32) {
                    int j = (c + 3) & 3;
                    mbar_expect_tx(mbar0 + 8u * j, CHUNK_B);
                    tma_g2s(buf_s + j * CHUNK_B, ksrc + (size_t)(c + 3) * 8192, CHUNK_B, mbar0 + 8u * j);
                }
                mbar_wait(mbar0 + 8u * (c & 3), (c >> 2) & 1);
                const float* Kc = bufs + (c & 3) * 8192;   // [16][512]
                const int h = c >> 2, d0 = (c & 3) * 16;
                if (d0 == 0) acc = 0.f;
                #pragma unroll
                for (int j = 0; j < 16; j++)
                    acc = fmaf(qs[h * DK + d0 + j], Kc[j * MEM_ + tid], acc);
                if (d0 == 48) sc[h][tid] = acc * 0.125f;
                __syncthreads();
            }

            // ---- prefetch first V chunks (buffers free), overlap with softmax ----
            const float* vsrc = g_vp + (size_t)bid * NH * MEM_ * DK;
            if (tid == 0) {
                #pragma unroll
                for (int j = 0; j < 3; j++) {
                    mbar_expect_tx(mbar0 + 8u * j, CHUNK_B);
                    tma_g2s(buf_s + j * CHUNK_B, vsrc + (size_t)j * 8192, CHUNK_B, mbar0 + 8u * j);
                }
            }

            // ---- softmax per head (64 threads/head) ----
            int h = tid >> 6, i = tid & 63;
            float mx = -3.4e38f;
            #pragma unroll
            for (int r = 0; r < 8; r++) mx = fmaxf(mx, sc[h][i + (r << 6)]);
            #pragma unroll
            for (int o = 16; o > 0; o >>= 1) mx = fmaxf(mx, __shfl_xor_sync(0xffffffffu, mx, o));
            if ((tid & 31) == 0) wred[tid >> 5] = mx;
            __syncthreads();
            float mh = fmaxf(wred[2 * h], wred[2 * h + 1]);

            float s = 0.f;
            #pragma unroll
            for (int r = 0; r < 8; r++) {
                int m = i + (r << 6);
                float e = expf(sc[h][m] - mh);
                sc[h][m] = e;
                s += e;
            }
            #pragma unroll
            for (int o = 16; o > 0; o >>= 1) s += __shfl_xor_sync(0xffffffffu, s, o);
            if ((tid & 31) == 0) wred2[tid >> 5] = s;
            __syncthreads();
            float inv = 1.f / (wred2[2 * h] + wred2[2 * h + 1]);
            if (i == 0) invs[h] = inv;
            __syncthreads();

            // ---- scores output: mean over heads (masked) ----
            {
                float sm = 0.f;
                #pragma unroll
                for (int hh = 0; hh < NH; hh++) sm += sc[hh][tid] * invs[hh];
                sm *= 0.125f;
                int run = t < lens[bid];
                out[OUT_S_OFF + ((size_t)t * BS + bid) * MEM_ + tid] = run ? sm : 0.f;
            }

            // ---- V phase: 32 chunks of [128 m][64 d]; thread = (g=tid>>6, d=tid&63)
            const int d = tid & 63, g = tid >> 6;
            float accv = 0.f;
            for (int c = 0; c < 32; c++) {
                if (tid == 0 && c + 3 < 32) {
                    int j = (c + 3) & 3;
                    mbar_expect_tx(mbar0 + 8u * j, CHUNK_B);
                    tma_g2s(buf_s + j * CHUNK_B, vsrc + (size_t)(c + 3) * 8192, CHUNK_B, mbar0 + 8u * j);
                }
                mbar_wait(mbar0 + 8u * (c & 3), (c >> 2) & 1);
                const float* Vc = bufs + (c & 3) * 8192;   // [128][64]
                const int vh = c >> 2, m0 = (c & 3) * 128;
                if (m0 == 0) accv = 0.f;
                const float* ph = &sc[vh][m0];
                #pragma unroll
                for (int k = 0; k < 16; k++) {
                    int ml = g * 16 + k;
                    accv = fmaf(ph[ml], Vc[ml * 64 + d], accv);
                }
                if (m0 == 384) red[vh][g][d] = accv;
                __syncthreads();
            }
            // final reduce over the 8 m-groups
            {
                int rh = tid >> 6, rd = tid & 63;
                float sum = 0.f;
                #pragma unroll
                for (int gg = 0; gg < 8; gg++) sum += red[rh][gg][rd];
                g_ctx[bid * D_ + rh * DK + rd] = sum * invs[rh];
            }
        }
        grid_bar();

        // ================= phase GRU (gate-triple tiling, fused activation) ======
        {
            GruSm& S = *(GruSm*)dynsm;
            const int j0 = bid * 4;
            const int kh = tid >> 8;
            const int r  = tid & 255;
            const int jj = r >> 6, bp = r & 63, b0 = bp * 2;
            const float* xsrc = kh ? hcur : g_ctx;
            const float* Wsrc = kh ? Whh  : Wih;
            float a[3][2] = {};
            for (int k0 = 0; k0 < H_; k0 += 32) {
                #pragma unroll
                for (int i = 0; i < 16; i++) {
                    int e = r + i * 256;
                    int kk = e & 31, bb = e >> 5;
                    S.Xs[kh][kk][bb] = xsrc[bb * H_ + k0 + kk];
                }
                #pragma unroll
                for (int i = 0; i < 2; i++) {
                    int e = r + i * 256;
                    if (e < 384) {
                        int row = e >> 5, kk = e & 31;
                        int g = row >> 2, jr = row & 3;
                        S.Ws[kh][row][kk] = Wsrc[((size_t)g * H_ + j0 + jr) * H_ + k0 + kk];
                    }
                }
                __syncthreads();
                #pragma unroll
                for (int kk = 0; kk < 32; kk++) {
                    float x0 = S.Xs[kh][kk][b0];
                    float x1 = S.Xs[kh][kk][b0 + 1];
                    #pragma unroll
                    for (int g = 0; g < 3; g++) {
                        float w = S.Ws[kh][g * 4 + jj][kk];
                        a[g][0] = fmaf(x0, w, a[g][0]);
                        a[g][1] = fmaf(x1, w, a[g][1]);
                    }
                }
                __syncthreads();
            }
            if (kh == 1) {
                #pragma unroll
                for (int g = 0; g < 3; g++) {
                    S.red[jj][bp][g * 2]     = a[g][0];
                    S.red[jj][bp][g * 2 + 1] = a[g][1];
                }
            }
            __syncthreads();
            if (kh == 0) {
                int j = j0 + jj;
                float bir = bih[j], biz = bih[j + H_], bin_ = bih[j + 2 * H_];
                float bhr = bhh[j], bhz = bhh[j + H_], bhn = bhh[j + 2 * H_];
                #pragma unroll
                for (int ib = 0; ib < 2; ib++) {
                    int b = b0 + ib;
                    float gir = a[0][ib] + bir;
                    float giz = a[1][ib] + biz;
                    float gin = a[2][ib] + bin_;
                    float ghr = S.red[jj][bp][0 * 2 + ib] + bhr;
                    float ghz = S.red[jj][bp][1 * 2 + ib] + bhz;
                    float ghn = S.red[jj][bp][2 * 2 + ib] + bhn;
                    float rr = sigmoidf_(gir + ghr);
                    float zz = sigmoidf_(giz + ghz);
                    float nn = tanhf(gin + rr * ghn);
                    float hold = hcur[b * H_ + j];
                    float hn = (1.f - zz) * nn + zz * hold;
                    hnext[b * H_ + j] = hn;
                    int run = t < lens[b];
                    out[OUT_H_OFF + ((size_t)t * BS + b) * H_ + j] = run ? hn : 0.f;
                }
            }
        }
        grid_bar();

        // ================= phase FC (+ partial argmax) ===========================
        if (bid < NFC) {
            FcSm& S = *(FcSm*)dynsm;
            const int n0 = bid * 8;
            const int tn = tid >> 7;
            const int b  = tid & 127;
            float acc0 = 0.f, acc1 = 0.f;
            for (int k0 = 0; k0 < H_; k0 += 32) {
                #pragma unroll
                for (int i = 0; i < 8; i++) {
                    int e = tid + i * 512;
                    int kk = e & 31, bb = e >> 5;
                    S.Xs[kk][bb] = hnext[bb * H_ + k0 + kk];
                }
                if (tid < 256) {
                    int row = tid >> 5, kk = tid & 31;
                    S.Ws[row][kk] = Wfc[(size_t)(n0 + row) * H_ + k0 + kk];
                }
                __syncthreads();
                const float* w0 = S.Ws[tn * 2];
                const float* w1 = S.Ws[tn * 2 + 1];
                #pragma unroll
                for (int kk = 0; kk < 32; kk++) {
                    float x = S.Xs[kk][b];
                    acc0 = fmaf(x, w0[kk], acc0);
                    acc1 = fmaf(x, w1[kk], acc1);
                }
                __syncthreads();
            }
            int na = n0 + tn * 2, nb = na + 1;
            float v0 = acc0 + bfc[na];
            float v1 = acc1 + bfc[nb];
            int run = t < lens[b];
            size_t ob = ((size_t)t * BS + b) * V_;
            out[ob + na] = run ? v0 : 0.f;
            out[ob + nb] = run ? v1 : 0.f;
            float lv = v0; int li = na;
            if (v1 > lv) { lv = v1; li = nb; }
            S.apv[tn][b] = lv;
            S.api[tn][b] = li;
            __syncthreads();
            if (tn == 0) {
                float bv = S.apv[0][b]; int bi = S.api[0][b];
                #pragma unroll
                for (int p = 1; p < 4; p++) {
                    float v = S.apv[p][b];
                    if (v > bv) { bv = v; bi = S.api[p][b]; }
                }
                g_pv[bid * BS + b] = bv;
                g_pi[bid * BS + b] = bi;
            }
        }
        grid_bar();
    }
}

// ---------------- launch ----------------
extern "C" void kernel_launch(void* const* d_in, const int* in_sizes, int n_in,
                              void* d_out, int out_size)
{
    const float* memory = (const float*)d_in[0];
    const float* emb    = (const float*)d_in[1];
    const float* Wq     = (const float*)d_in[2];
    const float* bq     = (const float*)d_in[3];
    const float* Wk     = (const float*)d_in[4];
    const float* bk     = (const float*)d_in[5];
    const float* Wv     = (const float*)d_in[6];
    const float* bv     = (const float*)d_in[7];
    const float* Wih    = (const float*)d_in[8];
    const float* Whh    = (const float*)d_in[9];
    const float* bih    = (const float*)d_in[10];
    const float* bhh    = (const float*)d_in[11];
    const float* Wfc    = (const float*)d_in[12];
    const float* bfc    = (const float*)d_in[13];
    const int*   lens   = (const int*)d_in[14];
    float* out = (float*)d_out;

    // Host-side, non-stream API: idempotent, called unconditionally (no static
    // guards allowed). Legal alongside graph capture since it is not a stream op.
    cudaFuncSetAttribute(decode_kernel, cudaFuncAttributeMaxDynamicSharedMemorySize, SMEM_TOTAL);

    init_kernel<<<128, 256>>>();
    kvproj_kernel<<<dim3(MEM_ / 64, D_ / 64, BS), 256>>>(memory, Wk, bk, Wv, bv);
    decode_kernel<<<NBLK, 512, SMEM_TOTAL>>>(emb, Wq, bq, Wih, Whh, bih, bhh, Wfc, bfc, lens, out);
}

// round 10
// speedup vs baseline: 1.7714x; 1.7714x over previous
#include <cuda_runtime.h>
#include <math.h>
#include <stdint.h>

#define V_   1000
#define H_   512
#define D_   512
#define NH   8
#define DK   64
#define MEM_ 512
#define BS   128
#define TMAX 160
#define NBLK 128
#define NFC  125

#define OUT_H_OFF (TMAX*BS*V_)
#define OUT_S_OFF (OUT_H_OFF + TMAX*BS*H_)

// ---- dynamic smem layout (float indices) ----
#define A_QS   0
#define A_SC   512
#define A_RED  4608
#define A_W1   8704
#define A_W2   8720
#define A_INV  8736
#define RING   8768          // 3 x 8192 floats (32KB each), 128B aligned
#define QX     0             // [128][132]
#define QTOK   16896
#define QAV    17024
#define QAI    17536
#define GX     0             // [2][128][64] swizzled
#define GP     0             // [2][8][12][128] partials (after GX freed)
#define FX     0             // [128][132]
#define RWQ    33376         // Wq resident [4][1024]
#define RWG    37472         // Wgru resident [24][512]
#define RWF    49760         // Wfc resident [8][512]
#define MBF    53856         // 3 mbarriers
#define SMEM_BYTES (53864*4)

__device__ float g_kt[(size_t)BS*NH*DK*MEM_];
__device__ float g_vp[(size_t)BS*NH*MEM_*DK];
__device__ float g_h2[2][BS*H_];
__device__ float g_q [BS*D_];
__device__ float g_ctx[BS*D_];
__device__ float g_pv[NFC*BS];
__device__ int   g_pi[NFC*BS];
__device__ unsigned g_bar_count;
__device__ volatile unsigned g_bar_gen;

__device__ __forceinline__ unsigned s2u(const void* p) {
    return (unsigned)__cvta_generic_to_shared(p);
}
__device__ __forceinline__ void mbar_init(unsigned a, unsigned cnt) {
    asm volatile("mbarrier.init.shared.b64 [%0], %1;" :: "r"(a), "r"(cnt) : "memory");
}
__device__ __forceinline__ void mbar_expect_tx(unsigned a, unsigned bytes) {
    asm volatile("mbarrier.arrive.expect_tx.shared.b64 _, [%0], %1;" :: "r"(a), "r"(bytes) : "memory");
}
__device__ __forceinline__ void mbar_wait(unsigned a, unsigned parity) {
    unsigned done;
    asm volatile("{\n\t.reg .pred p;\n\t"
        "mbarrier.try_wait.parity.acquire.cta.shared::cta.b64 p, [%1], %2, 0x989680;\n\t"
        "selp.b32 %0, 1, 0, p;\n\t}" : "=r"(done) : "r"(a), "r"(parity) : "memory");
    while (!done) {
        asm volatile("{\n\t.reg .pred p;\n\t"
            "mbarrier.try_wait.parity.acquire.cta.shared::cta.b64 p, [%1], %2, 0x989680;\n\t"
            "selp.b32 %0, 1, 0, p;\n\t}" : "=r"(done) : "r"(a), "r"(parity) : "memory");
    }
}
__device__ __forceinline__ void tma_g2s(unsigned dst, const void* src, unsigned bytes, unsigned mbar) {
    asm volatile("cp.async.bulk.shared::cluster.global.mbarrier::complete_tx::bytes [%0], [%1], %2, [%3];"
                 :: "r"(dst), "l"(src), "r"(bytes), "r"(mbar) : "memory");
}
__device__ __forceinline__ void fence_pa() {
    asm volatile("fence.proxy.async.shared::cta;" ::: "memory");
}
__device__ __forceinline__ float sigmoidf_(float x) { return 1.f / (1.f + expf(-x)); }

__global__ void init_kernel() {
    int i = blockIdx.x * blockDim.x + threadIdx.x;
    for (; i < 2 * BS * H_; i += gridDim.x * blockDim.x) ((float*)g_h2)[i] = 0.f;
}

__global__ void __launch_bounds__(256) kvproj_kernel(
    const float* __restrict__ memory, const float* __restrict__ Wk, const float* __restrict__ bk,
    const float* __restrict__ Wv, const float* __restrict__ bv)
{
    __shared__ float Xs[64][17], Ks[64][17], Vs[64][17];
    int m0 = blockIdx.x * 64, n0 = blockIdx.y * 64, b = blockIdx.z;
    int tid = threadIdx.x, tn = tid & 15, tm = tid >> 4;
    float accK[4][4] = {}, accV[4][4] = {};
    for (int k0 = 0; k0 < D_; k0 += 16) {
        #pragma unroll
        for (int i = 0; i < 4; i++) {
            int e = tid + i * 256, kk = e & 15, mm = e >> 4;
            Xs[mm][kk] = memory[((size_t)(m0 + mm) * BS + b) * D_ + k0 + kk];
            Ks[mm][kk] = Wk[(size_t)(n0 + mm) * D_ + k0 + kk];
            Vs[mm][kk] = Wv[(size_t)(n0 + mm) * D_ + k0 + kk];
        }
        __syncthreads();
        #pragma unroll
        for (int kk = 0; kk < 16; kk++) {
            float xv[4], kw[4], vw[4];
            #pragma unroll
            for (int i = 0; i < 4; i++) xv[i] = Xs[tm * 4 + i][kk];
            #pragma unroll
            for (int j = 0; j < 4; j++) { kw[j] = Ks[tn * 4 + j][kk]; vw[j] = Vs[tn * 4 + j][kk]; }
            #pragma unroll
            for (int i = 0; i < 4; i++)
                #pragma unroll
                for (int j = 0; j < 4; j++) {
                    accK[i][j] = fmaf(xv[i], kw[j], accK[i][j]);
                    accV[i][j] = fmaf(xv[i], vw[j], accV[i][j]);
                }
        }
        __syncthreads();
    }
    #pragma unroll
    for (int i = 0; i < 4; i++) {
        int m = m0 + tm * 4 + i;
        #pragma unroll
        for (int j = 0; j < 4; j++) {
            int n = n0 + tn * 4 + j, h = n >> 6, d = n & 63;
            g_kt[(((size_t)b * NH + h) * DK + d) * MEM_ + m] = accK[i][j] + bk[n];
            g_vp[(((size_t)b * NH + h) * MEM_ + m) * DK + d] = accV[i][j] + bv[n];
        }
    }
}

extern __shared__ __align__(128) float dynf[];

__device__ __forceinline__ void grid_bar() {
    __syncthreads();
    if (threadIdx.x == 0) {
        unsigned gen = g_bar_gen;
        __threadfence();
        unsigned ticket = atomicAdd(&g_bar_count, 1u);
        if (ticket == gridDim.x - 1) { g_bar_count = 0; __threadfence(); g_bar_gen = gen + 1; }
        else { while (g_bar_gen == gen) __nanosleep(32); __threadfence(); }
    }
    __syncthreads();
}

__global__ void __launch_bounds__(512, 1) decode_kernel(
    const float* __restrict__ emb,  const float* __restrict__ Wq,  const float* __restrict__ bq,
    const float* __restrict__ Wih,  const float* __restrict__ Whh,
    const float* __restrict__ bih,  const float* __restrict__ bhh,
    const float* __restrict__ Wfc,  const float* __restrict__ bfc,
    const int*   __restrict__ lens, float* __restrict__ out)
{
    const int bid = blockIdx.x, tid = threadIdx.x;
    const int wrp = tid >> 5, lane = tid & 31;
    const int n0q = bid * 4, j0 = bid * 4, n0f = bid * 8;
    const unsigned mb = s2u(&dynf[MBF]);
    const unsigned ring_s = s2u(&dynf[RING]);

    // resident weights
    for (int i = tid; i < 4 * 1024; i += 512)
        dynf[RWQ + i] = Wq[(size_t)(n0q + (i >> 10)) * (2 * H_) + (i & 1023)];
    for (int i = tid; i < 24 * 512; i += 512) {
        int r24 = i >> 9, k = i & 511, p = r24 / 12, r = r24 % 12, g = r >> 2, jj = r & 3;
        dynf[RWG + i] = (p ? Whh : Wih)[(size_t)(g * H_ + j0 + jj) * H_ + k];
    }
    if (bid < NFC)
        for (int i = tid; i < 8 * 512; i += 512)
            dynf[RWF + i] = Wfc[(size_t)(n0f + (i >> 9)) * H_ + (i & 511)];
    if (tid == 0) { mbar_init(mb, 1u); mbar_init(mb + 8, 1u); mbar_init(mb + 16, 1u); }
    __syncthreads();
    int p0 = 0, p1 = 0, p2 = 0;

    for (int t = 0; t < TMAX; t++) {
        const float* hcur = g_h2[t & 1];
        float* hnext = g_h2[(t + 1) & 1];

        // ========== Q: toks, then q = [emb[tok],h] @ Wq^T + bq ==========
        {
            int* TOK = (int*)&dynf[QTOK];
            if (t == 0) { if (tid < BS) TOK[tid] = 0; }
            else {
                float* AV = &dynf[QAV]; int* AI = (int*)&dynf[QAI];
                int l = tid >> 7, b = tid & 127;
                float bv = -3.4e38f; int bi = 0;
                for (int p = l; p < NFC; p += 4) {
                    float v = g_pv[p * BS + b]; int ix = g_pi[p * BS + b];
                    if (v > bv || (v == bv && ix < bi)) { bv = v; bi = ix; }
                }
                AV[l * 128 + b] = bv; AI[l * 128 + b] = bi;
                __syncthreads();
                if (tid < BS) {
                    float cv = AV[tid]; int ci = AI[tid];
                    #pragma unroll
                    for (int l2 = 1; l2 < 4; l2++) {
                        float v = AV[l2 * 128 + tid]; int ix = AI[l2 * 128 + tid];
                        if (v > cv || (v == cv && ix < ci)) { cv = v; ci = ix; }
                    }
                    TOK[tid] = ci;
                }
            }
            __syncthreads();
            float acc[4][8] = {};
            for (int c = 0; c < 8; c++) {
                #pragma unroll
                for (int i = 0; i < 8; i++) {
                    int e = tid + i * 512, b = e >> 5, k4 = e & 31;
                    const float* row = (c < 4) ? (emb + (size_t)TOK[b] * H_ + c * 128)
                                               : (hcur + b * H_ + (c - 4) * 128);
                    *(float4*)&dynf[QX + b * 132 + k4 * 4] = *(const float4*)(row + k4 * 4);
                }
                __syncthreads();
                #pragma unroll
                for (int j = 0; j < 4; j++) {
                    int kk = lane + 32 * j;
                    float wv[4];
                    #pragma unroll
                    for (int ni = 0; ni < 4; ni++) wv[ni] = dynf[RWQ + ni * 1024 + c * 128 + kk];
                    #pragma unroll
                    for (int bi = 0; bi < 8; bi++) {
                        float x = dynf[QX + (wrp * 8 + bi) * 132 + kk];
                        #pragma unroll
                        for (int ni = 0; ni < 4; ni++) acc[ni][bi] = fmaf(x, wv[ni], acc[ni][bi]);
                    }
                }
                __syncthreads();
            }
            #pragma unroll
            for (int j = 0; j < 32; j++) {
                int ni = j >> 3, bi = j & 7;
                float v = acc[ni][bi];
                #pragma unroll
                for (int o = 16; o > 0; o >>= 1) v += __shfl_xor_sync(0xffffffffu, v, o);
                if (lane == j) {
                    int n = n0q + ni, b = wrp * 8 + bi;
                    g_q[b * D_ + n] = v + bq[n];
                }
            }
        }
        grid_bar();

        // ========== ATT: unified 64-chunk TMA stream (32 K + 32 V) ==========
        {
            dynf[A_QS + tid] = g_q[bid * D_ + tid];
            __syncthreads();
            const float* ksrc = g_kt + (size_t)bid * NH * DK * MEM_;
            const float* vsrc = g_vp + (size_t)bid * NH * MEM_ * DK;
            if (tid == 0) {
                fence_pa();
                #pragma unroll
                for (int j = 0; j < 3; j++) {
                    mbar_expect_tx(mb + 8u * j, 32768);
                    tma_g2s(ring_s + j * 32768, ksrc + (size_t)j * 8192, 32768, mb + 8u * j);
                }
            }
            float acc = 0.f, accv = 0.f;
            const int vg = tid >> 6, vd = tid & 63;
            for (int c = 0; c < 64; c++) {
                int jb = c % 3, pj;
                if (jb == 0) { pj = p0; p0 ^= 1; }
                else if (jb == 1) { pj = p1; p1 ^= 1; }
                else { pj = p2; p2 ^= 1; }
                mbar_wait(mb + 8u * jb, pj);
                const float* Bf = &dynf[RING + jb * 8192];
                if (c < 32) {
                    int h = c >> 2, d0 = (c & 3) * 16;
                    if (d0 == 0) acc = 0.f;
                    #pragma unroll
                    for (int u = 0; u < 16; u++)
                        acc = fmaf(dynf[A_QS + h * DK + d0 + u], Bf[u * MEM_ + tid], acc);
                    if (d0 == 48) dynf[A_SC + h * MEM_ + tid] = acc * 0.125f;
                } else {
                    int cv = c - 32, vh = cv >> 2, m0 = (cv & 3) * 128;
                    if (m0 == 0) accv = 0.f;
                    const float* ph = &dynf[A_SC + vh * MEM_ + m0];
                    #pragma unroll
                    for (int u = 0; u < 16; u++) {
                        int ml = vg * 16 + u;
                        accv = fmaf(ph[ml], Bf[ml * 64 + vd], accv);
                    }
                    if (m0 == 384) dynf[A_RED + (vh * 8 + vg) * 64 + vd] = accv;
                }
                __syncthreads();
                if (c == 31) {
                    int h = tid >> 6, i = tid & 63;
                    float mx = -3.4e38f;
                    #pragma unroll
                    for (int r = 0; r < 8; r++) mx = fmaxf(mx, dynf[A_SC + h * MEM_ + i + (r << 6)]);
                    #pragma unroll
                    for (int o = 16; o > 0; o >>= 1) mx = fmaxf(mx, __shfl_xor_sync(0xffffffffu, mx, o));
                    if ((tid & 31) == 0) dynf[A_W1 + (tid >> 5)] = mx;
                    __syncthreads();
                    float mh = fmaxf(dynf[A_W1 + 2 * h], dynf[A_W1 + 2 * h + 1]);
                    float s = 0.f;
                    #pragma unroll
                    for (int r = 0; r < 8; r++) {
                        int m = i + (r << 6);
                        float e = expf(dynf[A_SC + h * MEM_ + m] - mh);
                        dynf[A_SC + h * MEM_ + m] = e;
                        s += e;
                    }
                    #pragma unroll
                    for (int o = 16; o > 0; o >>= 1) s += __shfl_xor_sync(0xffffffffu, s, o);
                    if ((tid & 31) == 0) dynf[A_W2 + (tid >> 5)] = s;
                    __syncthreads();
                    float inv = 1.f / (dynf[A_W2 + 2 * h] + dynf[A_W2 + 2 * h + 1]);
                    if (i == 0) dynf[A_INV + h] = inv;
                    __syncthreads();
                    float sm = 0.f;
                    #pragma unroll
                    for (int hh = 0; hh < NH; hh++)
                        sm += dynf[A_SC + hh * MEM_ + tid] * dynf[A_INV + hh];
                    sm *= 0.125f;
                    int run = t < lens[bid];
                    out[OUT_S_OFF + ((size_t)t * BS + bid) * MEM_ + tid] = run ? sm : 0.f;
                }
                if (tid == 0 && c + 3 < 64) {
                    int nc = c + 3, j2 = nc % 3;
                    const float* src = (nc < 32) ? (ksrc + (size_t)nc * 8192)
                                                 : (vsrc + (size_t)(nc - 32) * 8192);
                    mbar_expect_tx(mb + 8u * j2, 32768);
                    tma_g2s(ring_s + j2 * 32768, src, 32768, mb + 8u * j2);
                }
            }
            int rh = tid >> 6, rd = tid & 63;
            float sum = 0.f;
            #pragma unroll
            for (int gg = 0; gg < 8; gg++) sum += dynf[A_RED + (rh * 8 + gg) * 64 + rd];
            g_ctx[bid * D_ + rh * DK + rd] = sum * dynf[A_INV + rh];
        }
        grid_bar();

        // ========== GRU ==========
        {
            const int p = wrp >> 3, ks = wrp & 7;
            float ag[12][4] = {};
            for (int c = 0; c < 8; c++) {
                #pragma unroll
                for (int i = 0; i < 16; i++) {
                    int e = tid + i * 512;
                    int pth = e >> 12, r = (e >> 5) & 127, k2 = e & 31;
                    const float* src = pth ? hcur : g_ctx;
                    float2 v = *(const float2*)(src + r * 512 + c * 64 + k2 * 2);
                    *(float2*)&dynf[GX + pth * 8192 + r * 64 + ((k2 * 2) ^ ((r & 15) << 1))] = v;
                }
                __syncthreads();
                #pragma unroll
                for (int u = 0; u < 8; u++) {
                    int kk = ks * 8 + u, kg = c * 64 + kk;
                    float xv[4];
                    #pragma unroll
                    for (int bi = 0; bi < 4; bi++) {
                        int b = lane + bi * 32;
                        xv[bi] = dynf[GX + p * 8192 + b * 64 + (kk ^ ((b & 15) << 1))];
                    }
                    #pragma unroll
                    for (int row = 0; row < 12; row++) {
                        float wv = dynf[RWG + (p * 12 + row) * 512 + kg];
                        #pragma unroll
                        for (int bi = 0; bi < 4; bi++) ag[row][bi] = fmaf(xv[bi], wv, ag[row][bi]);
                    }
                }
                __syncthreads();
            }
            #pragma unroll
            for (int row = 0; row < 12; row++)
                #pragma unroll
                for (int bi = 0; bi < 4; bi++)
                    dynf[GP + ((p * 8 + ks) * 12 + row) * 128 + lane + bi * 32] = ag[row][bi];
            __syncthreads();
            {
                int b = tid & 127, jj = tid >> 7, j = j0 + jj;
                float gi[3], gh[3];
                #pragma unroll
                for (int g = 0; g < 3; g++) {
                    float s0 = 0.f, s1 = 0.f;
                    #pragma unroll
                    for (int ks2 = 0; ks2 < 8; ks2++) {
                        s0 += dynf[GP + ((0 * 8 + ks2) * 12 + g * 4 + jj) * 128 + b];
                        s1 += dynf[GP + ((1 * 8 + ks2) * 12 + g * 4 + jj) * 128 + b];
                    }
                    gi[g] = s0 + bih[g * H_ + j];
                    gh[g] = s1 + bhh[g * H_ + j];
                }
                float rr = sigmoidf_(gi[0] + gh[0]);
                float zz = sigmoidf_(gi[1] + gh[1]);
                float nn = tanhf(gi[2] + rr * gh[2]);
                float hold = hcur[b * H_ + j];
                float hn = (1.f - zz) * nn + zz * hold;
                hnext[b * H_ + j] = hn;
                int run = t < lens[b];
                out[OUT_H_OFF + ((size_t)t * BS + b) * H_ + j] = run ? hn : 0.f;
            }
        }
        grid_bar();

        // ========== FC + partial argmax ==========
        if (bid < NFC) {
            float af[8][8] = {};
            for (int c = 0; c < 4; c++) {
                #pragma unroll
                for (int i = 0; i < 8; i++) {
                    int e = tid + i * 512, b = e >> 5, k4 = e & 31;
                    *(float4*)&dynf[FX + b * 132 + k4 * 4] =
                        *(const float4*)(hnext + b * H_ + c * 128 + k4 * 4);
                }
                __syncthreads();
                #pragma unroll
                for (int j = 0; j < 4; j++) {
                    int kk = lane + 32 * j;
                    float wv[8];
                    #pragma unroll
                    for (int ni = 0; ni < 8; ni++) wv[ni] = dynf[RWF + ni * 512 + c * 128 + kk];
                    #pragma unroll
                    for (int bi = 0; bi < 8; bi++) {
                        float x = dynf[FX + (wrp * 8 + bi) * 132 + kk];
                        #pragma unroll
                        for (int ni = 0; ni < 8; ni++) af[ni][bi] = fmaf(x, wv[ni], af[ni][bi]);
                    }
                }
                __syncthreads();
            }
            float rr0 = 0.f, rr1 = 0.f;
            #pragma unroll
            for (int j = 0; j < 64; j++) {
                int ni = j >> 3, bi = j & 7;
                float v = af[ni][bi];
                #pragma unroll
                for (int o = 16; o > 0; o >>= 1) v += __shfl_xor_sync(0xffffffffu, v, o);
                if (lane == (j & 31)) { if (j < 32) rr0 = v; else rr1 = v; }
            }
            int bi = lane & 7, b = wrp * 8 + bi;
            int nA = n0f + (lane >> 3), nB = nA + 4;
            float vA = rr0 + bfc[nA], vB = rr1 + bfc[nB];
            int run = t < lens[b];
            size_t ob = ((size_t)t * BS + b) * V_;
            out[ob + nA] = run ? vA : 0.f;
            out[ob + nB] = run ? vB : 0.f;
            float mv = vA; int mi = nA;
            if (vB > mv) { mv = vB; mi = nB; }
            #pragma unroll
            for (int o = 8; o <= 16; o <<= 1) {
                float v2 = __shfl_xor_sync(0xffffffffu, mv, o);
                int   i2 = __shfl_xor_sync(0xffffffffu, mi, o);
                if (v2 > mv || (v2 == mv && i2 < mi)) { mv = v2; mi = i2; }
            }
            if (lane < 8) { g_pv[bid * BS + b] = mv; g_pi[bid * BS + b] = mi; }
        }
        grid_bar();
    }
}

extern "C" void kernel_launch(void* const* d_in, const int* in_sizes, int n_in,
                              void* d_out, int out_size)
{
    const float* memory = (const float*)d_in[0];
    const float* emb    = (const float*)d_in[1];
    const float* Wq     = (const float*)d_in[2];
    const float* bq     = (const float*)d_in[3];
    const float* Wk     = (const float*)d_in[4];
    const float* bk     = (const float*)d_in[5];
    const float* Wv     = (const float*)d_in[6];
    const float* bv     = (const float*)d_in[7];
    const float* Wih    = (const float*)d_in[8];
    const float* Whh    = (const float*)d_in[9];
    const float* bih    = (const float*)d_in[10];
    const float* bhh    = (const float*)d_in[11];
    const float* Wfc    = (const float*)d_in[12];
    const float* bfc    = (const float*)d_in[13];
    const int*   lens   = (const int*)d_in[14];
    float* out = (float*)d_out;

    cudaFuncSetAttribute(decode_kernel, cudaFuncAttributeMaxDynamicSharedMemorySize, SMEM_BYTES);

    init_kernel<<<128, 256>>>();
    kvproj_kernel<<<dim3(MEM_ / 64, D_ / 64, BS), 256>>>(memory, Wk, bk, Wv, bv);
    decode_kernel<<<NBLK, 512, SMEM_BYTES>>>(emb, Wq, bq, Wih, Whh, bih, bhh, Wfc, bfc, lens, out);
}

// round 11
// speedup vs baseline: 1.8116x; 1.0227x over previous
#include <cuda_runtime.h>
#include <math.h>
#include <stdint.h>

#define V_   1000
#define H_   512
#define D_   512
#define NH   8
#define DK   64
#define MEM_ 512
#define BS   128
#define TMAX 160
#define NBLK 128
#define NFC  125

#define OUT_H_OFF (TMAX*BS*V_)
#define OUT_S_OFF (OUT_H_OFF + TMAX*BS*H_)

// ---- dynamic smem layout (float indices) ----
#define A_QS   0
#define A_SC   512
#define A_RED  4608
#define A_W1   8704
#define A_W2   8720
#define A_INV  8736
#define RING   8768          // 3 x 8192 floats (32KB each), 128B aligned
#define QX     0             // [128][132]
#define QTOK   16896
#define QAV    17024
#define QAI    17536
#define GX     0             // [2][128][64] swizzled
#define GP     0             // [2][8][12][128] partials (after GX freed)
#define FX     0             // [128][132]
#define RWQ    33376         // Wq resident [4][1024]
#define RWG    37472         // Wgru resident [24][512]
#define RWF    49760         // Wfc resident [8][512]
#define MBF    53856         // 3 mbarriers
#define SMEM_BYTES (53864*4)

__device__ float g_kt[(size_t)BS*NH*DK*MEM_];
__device__ float g_vp[(size_t)BS*NH*MEM_*DK];
__device__ float g_h2[2][BS*H_];
__device__ float g_q [BS*D_];
__device__ float g_ctx[BS*D_];
__device__ float g_pv[NFC*BS];
__device__ int   g_pi[NFC*BS];
__device__ unsigned g_bar_count;
__device__ volatile unsigned g_bar_gen;

__device__ __forceinline__ unsigned s2u(const void* p) {
    return (unsigned)__cvta_generic_to_shared(p);
}
__device__ __forceinline__ void mbar_init(unsigned a, unsigned cnt) {
    asm volatile("mbarrier.init.shared.b64 [%0], %1;" :: "r"(a), "r"(cnt) : "memory");
}
__device__ __forceinline__ void mbar_expect_tx(unsigned a, unsigned bytes) {
    asm volatile("mbarrier.arrive.expect_tx.shared.b64 _, [%0], %1;" :: "r"(a), "r"(bytes) : "memory");
}
__device__ __forceinline__ void mbar_wait(unsigned a, unsigned parity) {
    unsigned done;
    asm volatile("{\n\t.reg .pred p;\n\t"
        "mbarrier.try_wait.parity.acquire.cta.shared::cta.b64 p, [%1], %2, 0x989680;\n\t"
        "selp.b32 %0, 1, 0, p;\n\t}" : "=r"(done) : "r"(a), "r"(parity) : "memory");
    while (!done) {
        asm volatile("{\n\t.reg .pred p;\n\t"
            "mbarrier.try_wait.parity.acquire.cta.shared::cta.b64 p, [%1], %2, 0x989680;\n\t"
            "selp.b32 %0, 1, 0, p;\n\t}" : "=r"(done) : "r"(a), "r"(parity) : "memory");
    }
}
__device__ __forceinline__ void tma_g2s(unsigned dst, const void* src, unsigned bytes, unsigned mbar) {
    asm volatile("cp.async.bulk.shared::cluster.global.mbarrier::complete_tx::bytes [%0], [%1], %2, [%3];"
                 :: "r"(dst), "l"(src), "r"(bytes), "r"(mbar) : "memory");
}
__device__ __forceinline__ void fence_pa() {
    asm volatile("fence.proxy.async.shared::cta;" ::: "memory");
}
__device__ __forceinline__ float sigmoidf_(float x) { return 1.f / (1.f + expf(-x)); }

__global__ void init_kernel() {
    int i = blockIdx.x * blockDim.x + threadIdx.x;
    for (; i < 2 * BS * H_; i += gridDim.x * blockDim.x) ((float*)g_h2)[i] = 0.f;
}

// ---- KV projection: 128m x 64n tile, 8x4 per thread, float4 LDS operands ----
__global__ void __launch_bounds__(256) kvproj_kernel(
    const float* __restrict__ memory, const float* __restrict__ Wk, const float* __restrict__ bk,
    const float* __restrict__ Wv, const float* __restrict__ bv)
{
    __shared__ float Xs[16][132];   // [k][m], padded
    __shared__ float Ks[16][68];    // [k][n]
    __shared__ float Vs[16][68];
    const int m0 = blockIdx.x * 128, n0 = blockIdx.y * 64, b = blockIdx.z;
    const int tid = threadIdx.x, tn = tid & 15, tm = tid >> 4;
    float accK[8][4] = {}, accV[8][4] = {};

    for (int k0 = 0; k0 < D_; k0 += 16) {
        #pragma unroll
        for (int i = 0; i < 8; i++) {
            int e = tid + i * 256, kk = e & 15, mm = e >> 4;   // mm 0..127
            Xs[kk][mm] = memory[((size_t)(m0 + mm) * BS + b) * D_ + k0 + kk];
        }
        #pragma unroll
        for (int i = 0; i < 4; i++) {
            int e = tid + i * 256, kk = e & 15, nn = e >> 4;   // nn 0..63
            Ks[kk][nn] = Wk[(size_t)(n0 + nn) * D_ + k0 + kk];
            Vs[kk][nn] = Wv[(size_t)(n0 + nn) * D_ + k0 + kk];
        }
        __syncthreads();
        #pragma unroll
        for (int kk = 0; kk < 16; kk++) {
            float4 xa = *(const float4*)&Xs[kk][tm * 8];
            float4 xb = *(const float4*)&Xs[kk][tm * 8 + 4];
            float4 kw = *(const float4*)&Ks[kk][tn * 4];
            float4 vw = *(const float4*)&Vs[kk][tn * 4];
            float xv[8] = {xa.x, xa.y, xa.z, xa.w, xb.x, xb.y, xb.z, xb.w};
            float kwv[4] = {kw.x, kw.y, kw.z, kw.w};
            float vwv[4] = {vw.x, vw.y, vw.z, vw.w};
            #pragma unroll
            for (int i = 0; i < 8; i++)
                #pragma unroll
                for (int j = 0; j < 4; j++) {
                    accK[i][j] = fmaf(xv[i], kwv[j], accK[i][j]);
                    accV[i][j] = fmaf(xv[i], vwv[j], accV[i][j]);
                }
        }
        __syncthreads();
    }
    #pragma unroll
    for (int j = 0; j < 4; j++) {
        int n = n0 + tn * 4 + j, h = n >> 6, d = n & 63;
        float bkv = bk[n], bvv = bv[n];
        #pragma unroll
        for (int i = 0; i < 8; i++) {
            int m = m0 + tm * 8 + i;
            g_kt[(((size_t)b * NH + h) * DK + d) * MEM_ + m] = accK[i][j] + bkv;
            g_vp[(((size_t)b * NH + h) * MEM_ + m) * DK + d] = accV[i][j] + bvv;
        }
    }
}

extern __shared__ __align__(128) float dynf[];

__device__ __forceinline__ void grid_bar() {
    __syncthreads();
    if (threadIdx.x == 0) {
        unsigned gen = g_bar_gen;
        __threadfence();
        unsigned ticket = atomicAdd(&g_bar_count, 1u);
        if (ticket == gridDim.x - 1) { g_bar_count = 0; __threadfence(); g_bar_gen = gen + 1; }
        else { while (g_bar_gen == gen) __nanosleep(32); __threadfence(); }
    }
    __syncthreads();
}

__global__ void __launch_bounds__(512, 1) decode_kernel(
    const float* __restrict__ emb,  const float* __restrict__ Wq,  const float* __restrict__ bq,
    const float* __restrict__ Wih,  const float* __restrict__ Whh,
    const float* __restrict__ bih,  const float* __restrict__ bhh,
    const float* __restrict__ Wfc,  const float* __restrict__ bfc,
    const int*   __restrict__ lens, float* __restrict__ out)
{
    const int bid = blockIdx.x, tid = threadIdx.x;
    const int wrp = tid >> 5, lane = tid & 31;
    const int n0q = bid * 4, j0 = bid * 4, n0f = bid * 8;
    const unsigned mb = s2u(&dynf[MBF]);
    const unsigned ring_s = s2u(&dynf[RING]);

    // resident weights
    for (int i = tid; i < 4 * 1024; i += 512)
        dynf[RWQ + i] = Wq[(size_t)(n0q + (i >> 10)) * (2 * H_) + (i & 1023)];
    for (int i = tid; i < 24 * 512; i += 512) {
        int r24 = i >> 9, k = i & 511, p = r24 / 12, r = r24 % 12, g = r >> 2, jj = r & 3;
        dynf[RWG + i] = (p ? Whh : Wih)[(size_t)(g * H_ + j0 + jj) * H_ + k];
    }
    if (bid < NFC)
        for (int i = tid; i < 8 * 512; i += 512)
            dynf[RWF + i] = Wfc[(size_t)(n0f + (i >> 9)) * H_ + (i & 511)];
    if (tid == 0) { mbar_init(mb, 1u); mbar_init(mb + 8, 1u); mbar_init(mb + 16, 1u); }
    __syncthreads();
    int p0 = 0, p1 = 0, p2 = 0;

    for (int t = 0; t < TMAX; t++) {
        const float* hcur = g_h2[t & 1];
        float* hnext = g_h2[(t + 1) & 1];

        // ========== Q: toks, then q = [emb[tok],h] @ Wq^T + bq ==========
        {
            int* TOK = (int*)&dynf[QTOK];
            if (t == 0) { if (tid < BS) TOK[tid] = 0; }
            else {
                float* AV = &dynf[QAV]; int* AI = (int*)&dynf[QAI];
                int l = tid >> 7, b = tid & 127;
                float bv = -3.4e38f; int bi = 0;
                for (int p = l; p < NFC; p += 4) {
                    float v = g_pv[p * BS + b]; int ix = g_pi[p * BS + b];
                    if (v > bv || (v == bv && ix < bi)) { bv = v; bi = ix; }
                }
                AV[l * 128 + b] = bv; AI[l * 128 + b] = bi;
                __syncthreads();
                if (tid < BS) {
                    float cv = AV[tid]; int ci = AI[tid];
                    #pragma unroll
                    for (int l2 = 1; l2 < 4; l2++) {
                        float v = AV[l2 * 128 + tid]; int ix = AI[l2 * 128 + tid];
                        if (v > cv || (v == cv && ix < ci)) { cv = v; ci = ix; }
                    }
                    TOK[tid] = ci;
                }
            }
            __syncthreads();
            float acc[4][8] = {};
            for (int c = 0; c < 8; c++) {
                #pragma unroll
                for (int i = 0; i < 8; i++) {
                    int e = tid + i * 512, b = e >> 5, k4 = e & 31;
                    const float* row = (c < 4) ? (emb + (size_t)TOK[b] * H_ + c * 128)
                                               : (hcur + b * H_ + (c - 4) * 128);
                    *(float4*)&dynf[QX + b * 132 + k4 * 4] = *(const float4*)(row + k4 * 4);
                }
                __syncthreads();
                #pragma unroll
                for (int j = 0; j < 4; j++) {
                    int kk = lane + 32 * j;
                    float wv[4];
                    #pragma unroll
                    for (int ni = 0; ni < 4; ni++) wv[ni] = dynf[RWQ + ni * 1024 + c * 128 + kk];
                    #pragma unroll
                    for (int bi = 0; bi < 8; bi++) {
                        float x = dynf[QX + (wrp * 8 + bi) * 132 + kk];
                        #pragma unroll
                        for (int ni = 0; ni < 4; ni++) acc[ni][bi] = fmaf(x, wv[ni], acc[ni][bi]);
                    }
                }
                __syncthreads();
            }
            #pragma unroll
            for (int j = 0; j < 32; j++) {
                int ni = j >> 3, bi = j & 7;
                float v = acc[ni][bi];
                #pragma unroll
                for (int o = 16; o > 0; o >>= 1) v += __shfl_xor_sync(0xffffffffu, v, o);
                if (lane == j) {
                    int n = n0q + ni, b = wrp * 8 + bi;
                    g_q[b * D_ + n] = v + bq[n];
                }
            }
        }
        grid_bar();

        // ========== ATT: unified 64-chunk TMA stream (32 K + 32 V) ==========
        {
            dynf[A_QS + tid] = g_q[bid * D_ + tid];
            __syncthreads();
            const float* ksrc = g_kt + (size_t)bid * NH * DK * MEM_;
            const float* vsrc = g_vp + (size_t)bid * NH * MEM_ * DK;
            if (tid == 0) {
                fence_pa();
                #pragma unroll
                for (int j = 0; j < 3; j++) {
                    mbar_expect_tx(mb + 8u * j, 32768);
                    tma_g2s(ring_s + j * 32768, ksrc + (size_t)j * 8192, 32768, mb + 8u * j);
                }
            }
            float acc = 0.f, accv = 0.f;
            const int vg = tid >> 6, vd = tid & 63;
            for (int c = 0; c < 64; c++) {
                int jb = c % 3, pj;
                if (jb == 0) { pj = p0; p0 ^= 1; }
                else if (jb == 1) { pj = p1; p1 ^= 1; }
                else { pj = p2; p2 ^= 1; }
                mbar_wait(mb + 8u * jb, pj);
                const float* Bf = &dynf[RING + jb * 8192];
                if (c < 32) {
                    int h = c >> 2, d0 = (c & 3) * 16;
                    if (d0 == 0) acc = 0.f;
                    #pragma unroll
                    for (int u = 0; u < 16; u++)
                        acc = fmaf(dynf[A_QS + h * DK + d0 + u], Bf[u * MEM_ + tid], acc);
                    if (d0 == 48) dynf[A_SC + h * MEM_ + tid] = acc * 0.125f;
                } else {
                    int cv = c - 32, vh = cv >> 2, m0 = (cv & 3) * 128;
                    if (m0 == 0) accv = 0.f;
                    const float* ph = &dynf[A_SC + vh * MEM_ + m0];
                    #pragma unroll
                    for (int u = 0; u < 16; u++) {
                        int ml = vg * 16 + u;
                        accv = fmaf(ph[ml], Bf[ml * 64 + vd], accv);
                    }
                    if (m0 == 384) dynf[A_RED + (vh * 8 + vg) * 64 + vd] = accv;
                }
                __syncthreads();
                if (c == 31) {
                    int h = tid >> 6, i = tid & 63;
                    float mx = -3.4e38f;
                    #pragma unroll
                    for (int r = 0; r < 8; r++) mx = fmaxf(mx, dynf[A_SC + h * MEM_ + i + (r << 6)]);
                    #pragma unroll
                    for (int o = 16; o > 0; o >>= 1) mx = fmaxf(mx, __shfl_xor_sync(0xffffffffu, mx, o));
                    if ((tid & 31) == 0) dynf[A_W1 + (tid >> 5)] = mx;
                    __syncthreads();
                    float mh = fmaxf(dynf[A_W1 + 2 * h], dynf[A_W1 + 2 * h + 1]);
                    float s = 0.f;
                    #pragma unroll
                    for (int r = 0; r < 8; r++) {
                        int m = i + (r << 6);
                        float e = expf(dynf[A_SC + h * MEM_ + m] - mh);
                        dynf[A_SC + h * MEM_ + m] = e;
                        s += e;
                    }
                    #pragma unroll
                    for (int o = 16; o > 0; o >>= 1) s += __shfl_xor_sync(0xffffffffu, s, o);
                    if ((tid & 31) == 0) dynf[A_W2 + (tid >> 5)] = s;
                    __syncthreads();
                    float inv = 1.f / (dynf[A_W2 + 2 * h] + dynf[A_W2 + 2 * h + 1]);
                    if (i == 0) dynf[A_INV + h] = inv;
                    __syncthreads();
                    float sm = 0.f;
                    #pragma unroll
                    for (int hh = 0; hh < NH; hh++)
                        sm += dynf[A_SC + hh * MEM_ + tid] * dynf[A_INV + hh];
                    sm *= 0.125f;
                    int run = t < lens[bid];
                    out[OUT_S_OFF + ((size_t)t * BS + bid) * MEM_ + tid] = run ? sm : 0.f;
                }
                if (tid == 0 && c + 3 < 64) {
                    int nc = c + 3, j2 = nc % 3;
                    const float* src = (nc < 32) ? (ksrc + (size_t)nc * 8192)
                                                 : (vsrc + (size_t)(nc - 32) * 8192);
                    mbar_expect_tx(mb + 8u * j2, 32768);
                    tma_g2s(ring_s + j2 * 32768, src, 32768, mb + 8u * j2);
                }
            }
            int rh = tid >> 6, rd = tid & 63;
            float sum = 0.f;
            #pragma unroll
            for (int gg = 0; gg < 8; gg++) sum += dynf[A_RED + (rh * 8 + gg) * 64 + rd];
            g_ctx[bid * D_ + rh * DK + rd] = sum * dynf[A_INV + rh];
        }
        grid_bar();

        // ========== GRU ==========
        {
            const int p = wrp >> 3, ks = wrp & 7;
            float ag[12][4] = {};
            for (int c = 0; c < 8; c++) {
                #pragma unroll
                for (int i = 0; i < 16; i++) {
                    int e = tid + i * 512;
                    int pth = e >> 12, r = (e >> 5) & 127, k2 = e & 31;
                    const float* src = pth ? hcur : g_ctx;
                    float2 v = *(const float2*)(src + r * 512 + c * 64 + k2 * 2);
                    *(float2*)&dynf[GX + pth * 8192 + r * 64 + ((k2 * 2) ^ ((r & 15) << 1))] = v;
                }
                __syncthreads();
                #pragma unroll
                for (int u = 0; u < 8; u++) {
                    int kk = ks * 8 + u, kg = c * 64 + kk;
                    float xv[4];
                    #pragma unroll
                    for (int bi = 0; bi < 4; bi++) {
                        int b = lane + bi * 32;
                        xv[bi] = dynf[GX + p * 8192 + b * 64 + (kk ^ ((b & 15) << 1))];
                    }
                    #pragma unroll
                    for (int row = 0; row < 12; row++) {
                        float wv = dynf[RWG + (p * 12 + row) * 512 + kg];
                        #pragma unroll
                        for (int bi = 0; bi < 4; bi++) ag[row][bi] = fmaf(xv[bi], wv, ag[row][bi]);
                    }
                }
                __syncthreads();
            }
            #pragma unroll
            for (int row = 0; row < 12; row++)
                #pragma unroll
                for (int bi = 0; bi < 4; bi++)
                    dynf[GP + ((p * 8 + ks) * 12 + row) * 128 + lane + bi * 32] = ag[row][bi];
            __syncthreads();
            {
                int b = tid & 127, jj = tid >> 7, j = j0 + jj;
                float gi[3], gh[3];
                #pragma unroll
                for (int g = 0; g < 3; g++) {
                    float s0 = 0.f, s1 = 0.f;
                    #pragma unroll
                    for (int ks2 = 0; ks2 < 8; ks2++) {
                        s0 += dynf[GP + ((0 * 8 + ks2) * 12 + g * 4 + jj) * 128 + b];
                        s1 += dynf[GP + ((1 * 8 + ks2) * 12 + g * 4 + jj) * 128 + b];
                    }
                    gi[g] = s0 + bih[g * H_ + j];
                    gh[g] = s1 + bhh[g * H_ + j];
                }
                float rr = sigmoidf_(gi[0] + gh[0]);
                float zz = sigmoidf_(gi[1] + gh[1]);
                float nn = tanhf(gi[2] + rr * gh[2]);
                float hold = hcur[b * H_ + j];
                float hn = (1.f - zz) * nn + zz * hold;
                hnext[b * H_ + j] = hn;
                int run = t < lens[b];
                out[OUT_H_OFF + ((size_t)t * BS + b) * H_ + j] = run ? hn : 0.f;
            }
        }
        grid_bar();

        // ========== FC + partial argmax ==========
        if (bid < NFC) {
            float af[8][8] = {};
            for (int c = 0; c < 4; c++) {
                #pragma unroll
                for (int i = 0; i < 8; i++) {
                    int e = tid + i * 512, b = e >> 5, k4 = e & 31;
                    *(float4*)&dynf[FX + b * 132 + k4 * 4] =
                        *(const float4*)(hnext + b * H_ + c * 128 + k4 * 4);
                }
                __syncthreads();
                #pragma unroll
                for (int j = 0; j < 4; j++) {
                    int kk = lane + 32 * j;
                    float wv[8];
                    #pragma unroll
                    for (int ni = 0; ni < 8; ni++) wv[ni] = dynf[RWF + ni * 512 + c * 128 + kk];
                    #pragma unroll
                    for (int bi = 0; bi < 8; bi++) {
                        float x = dynf[FX + (wrp * 8 + bi) * 132 + kk];
                        #pragma unroll
                        for (int ni = 0; ni < 8; ni++) af[ni][bi] = fmaf(x, wv[ni], af[ni][bi]);
                    }
                }
                __syncthreads();
            }
            float rr0 = 0.f, rr1 = 0.f;
            #pragma unroll
            for (int j = 0; j < 64; j++) {
                int ni = j >> 3, bi = j & 7;
                float v = af[ni][bi];
                #pragma unroll
                for (int o = 16; o > 0; o >>= 1) v += __shfl_xor_sync(0xffffffffu, v, o);
                if (lane == (j & 31)) { if (j < 32) rr0 = v; else rr1 = v; }
            }
            int bi = lane & 7, b = wrp * 8 + bi;
            int nA = n0f + (lane >> 3), nB = nA + 4;
            float vA = rr0 + bfc[nA], vB = rr1 + bfc[nB];
            int run = t < lens[b];
            size_t ob = ((size_t)t * BS + b) * V_;
            out[ob + nA] = run ? vA : 0.f;
            out[ob + nB] = run ? vB : 0.f;
            float mv = vA; int mi = nA;
            if (vB > mv) { mv = vB; mi = nB; }
            #pragma unroll
            for (int o = 8; o <= 16; o <<= 1) {
                float v2 = __shfl_xor_sync(0xffffffffu, mv, o);
                int   i2 = __shfl_xor_sync(0xffffffffu, mi, o);
                if (v2 > mv || (v2 == mv && i2 < mi)) { mv = v2; mi = i2; }
            }
            if (lane < 8) { g_pv[bid * BS + b] = mv; g_pi[bid * BS + b] = mi; }
        }
        grid_bar();
    }
}

extern "C" void kernel_launch(void* const* d_in, const int* in_sizes, int n_in,
                              void* d_out, int out_size)
{
    const float* memory = (const float*)d_in[0];
    const float* emb    = (const float*)d_in[1];
    const float* Wq     = (const float*)d_in[2];
    const float* bq     = (const float*)d_in[3];
    const float* Wk     = (const float*)d_in[4];
    const float* bk     = (const float*)d_in[5];
    const float* Wv     = (const float*)d_in[6];
    const float* bv     = (const float*)d_in[7];
    const float* Wih    = (const float*)d_in[8];
    const float* Whh    = (const float*)d_in[9];
    const float* bih    = (const float*)d_in[10];
    const float* bhh    = (const float*)d_in[11];
    const float* Wfc    = (const float*)d_in[12];
    const float* bfc    = (const float*)d_in[13];
    const int*   lens   = (const int*)d_in[14];
    float* out = (float*)d_out;

    cudaFuncSetAttribute(decode_kernel, cudaFuncAttributeMaxDynamicSharedMemorySize, SMEM_BYTES);

    init_kernel<<<128, 256>>>();
    kvproj_kernel<<<dim3(MEM_ / 128, D_ / 64, BS), 256>>>(memory, Wk, bk, Wv, bv);
    decode_kernel<<<NBLK, 512, SMEM_BYTES>>>(emb, Wq, bq, Wih, Whh, bih, bhh, Wfc, bfc, lens, out);
}

// round 12
// speedup vs baseline: 1.8826x; 1.0392x over previous
#include <cuda_runtime.h>
#include <math.h>
#include <stdint.h>

#define V_   1000
#define H_   512
#define D_   512
#define NH   8
#define DK   64
#define MEM_ 512
#define BS   128
#define TMAX 160
#define NBLK 128
#define NFC  125

#define OUT_H_OFF (TMAX*BS*V_)
#define OUT_S_OFF (OUT_H_OFF + TMAX*BS*H_)

// ---- dynamic smem layout (float indices) ----
#define A_QS   0
#define A_SC   512
#define A_RED  4608
#define A_W1   8704
#define A_W2   8720
#define A_INV  8736
#define RING   8768          // 3 x 8192 floats (32KB each)
#define QX     0             // [128][132]
#define QTOK   16896
#define QAV    17024
#define QAI    17536
#define GX     0             // [128][64] swizzled
#define GP     0             // [16][12][128] partials (after GX reads done)
#define FX     0             // [128][132]
#define RWQ    33376         // Wq h-part resident [4][512]
#define RWG    37472         // Wgru resident [24][512] (rows 0-11 Wih, 12-23 Whh)
#define RWF    49760         // Wfc resident [8][512]
#define MBF    53856         // 3 mbarriers
#define SMEM_BYTES (53864*4)

__device__ float g_kt[(size_t)BS*NH*DK*MEM_];
__device__ float g_vp[(size_t)BS*NH*MEM_*DK];
__device__ float g_qe[(size_t)V_*D_];          // emb @ Wq[:, :512]^T
__device__ float g_h2[2][BS*H_];
__device__ float g_q [BS*D_];
__device__ float g_ctx[BS*D_];
__device__ float g_pv[NFC*BS];
__device__ int   g_pi[NFC*BS];
__device__ unsigned g_bar_count;
__device__ volatile unsigned g_bar_gen;

__device__ __forceinline__ unsigned s2u(const void* p) {
    return (unsigned)__cvta_generic_to_shared(p);
}
__device__ __forceinline__ void mbar_init(unsigned a, unsigned cnt) {
    asm volatile("mbarrier.init.shared.b64 [%0], %1;" :: "r"(a), "r"(cnt) : "memory");
}
__device__ __forceinline__ void mbar_expect_tx(unsigned a, unsigned bytes) {
    asm volatile("mbarrier.arrive.expect_tx.shared.b64 _, [%0], %1;" :: "r"(a), "r"(bytes) : "memory");
}
__device__ __forceinline__ void mbar_wait(unsigned a, unsigned parity) {
    unsigned done;
    asm volatile("{\n\t.reg .pred p;\n\t"
        "mbarrier.try_wait.parity.acquire.cta.shared::cta.b64 p, [%1], %2, 0x989680;\n\t"
        "selp.b32 %0, 1, 0, p;\n\t}" : "=r"(done) : "r"(a), "r"(parity) : "memory");
    while (!done) {
        asm volatile("{\n\t.reg .pred p;\n\t"
            "mbarrier.try_wait.parity.acquire.cta.shared::cta.b64 p, [%1], %2, 0x989680;\n\t"
            "selp.b32 %0, 1, 0, p;\n\t}" : "=r"(done) : "r"(a), "r"(parity) : "memory");
    }
}
__device__ __forceinline__ void tma_g2s(unsigned dst, const void* src, unsigned bytes, unsigned mbar) {
    asm volatile("cp.async.bulk.shared::cluster.global.mbarrier::complete_tx::bytes [%0], [%1], %2, [%3];"
                 :: "r"(dst), "l"(src), "r"(bytes), "r"(mbar) : "memory");
}
__device__ __forceinline__ void fence_pa() {
    asm volatile("fence.proxy.async.shared::cta;" ::: "memory");
}
__device__ __forceinline__ float sigmoidf_(float x) { return 1.f / (1.f + expf(-x)); }

__global__ void init_kernel() {
    int i = blockIdx.x * blockDim.x + threadIdx.x;
    for (; i < 2 * BS * H_; i += gridDim.x * blockDim.x) ((float*)g_h2)[i] = 0.f;
}

// ---- qe = emb @ Wq[:, :512]^T  (once) ----
__global__ void __launch_bounds__(256) qe_kernel(const float* __restrict__ emb,
                                                 const float* __restrict__ Wq)
{
    __shared__ float Es[16][68], Qs[16][68];
    int v0 = blockIdx.x * 64, n0 = blockIdx.y * 64;
    int tid = threadIdx.x, tn = tid & 15, tm = tid >> 4;
    float acc[4][4] = {};
    for (int k0 = 0; k0 < 512; k0 += 16) {
        #pragma unroll
        for (int i = 0; i < 4; i++) {
            int e = tid + i * 256, kk = e & 15, mm = e >> 4;
            int v = v0 + mm;
            Es[kk][mm] = (v < V_) ? emb[(size_t)v * H_ + k0 + kk] : 0.f;
            Qs[kk][mm] = Wq[(size_t)(n0 + mm) * (2 * H_) + k0 + kk];
        }
        __syncthreads();
        #pragma unroll
        for (int kk = 0; kk < 16; kk++) {
            float4 xa = *(const float4*)&Es[kk][tm * 4];
            float4 wa = *(const float4*)&Qs[kk][tn * 4];
            float xv[4] = {xa.x, xa.y, xa.z, xa.w};
            float wv[4] = {wa.x, wa.y, wa.z, wa.w};
            #pragma unroll
            for (int i = 0; i < 4; i++)
                #pragma unroll
                for (int j = 0; j < 4; j++)
                    acc[i][j] = fmaf(xv[i], wv[j], acc[i][j]);
        }
        __syncthreads();
    }
    #pragma unroll
    for (int i = 0; i < 4; i++) {
        int v = v0 + tm * 4 + i;
        if (v < V_)
            #pragma unroll
            for (int j = 0; j < 4; j++)
                g_qe[(size_t)v * D_ + n0 + tn * 4 + j] = acc[i][j];
    }
}

// ---- KV projection ----
__global__ void __launch_bounds__(256) kvproj_kernel(
    const float* __restrict__ memory, const float* __restrict__ Wk, const float* __restrict__ bk,
    const float* __restrict__ Wv, const float* __restrict__ bv)
{
    __shared__ float Xs[16][132];
    __shared__ float Ks[16][68];
    __shared__ float Vs[16][68];
    const int m0 = blockIdx.x * 128, n0 = blockIdx.y * 64, b = blockIdx.z;
    const int tid = threadIdx.x, tn = tid & 15, tm = tid >> 4;
    float accK[8][4] = {}, accV[8][4] = {};

    for (int k0 = 0; k0 < D_; k0 += 16) {
        #pragma unroll
        for (int i = 0; i < 8; i++) {
            int e = tid + i * 256, kk = e & 15, mm = e >> 4;
            Xs[kk][mm] = memory[((size_t)(m0 + mm) * BS + b) * D_ + k0 + kk];
        }
        #pragma unroll
        for (int i = 0; i < 4; i++) {
            int e = tid + i * 256, kk = e & 15, nn = e >> 4;
            Ks[kk][nn] = Wk[(size_t)(n0 + nn) * D_ + k0 + kk];
            Vs[kk][nn] = Wv[(size_t)(n0 + nn) * D_ + k0 + kk];
        }
        __syncthreads();
        #pragma unroll
        for (int kk = 0; kk < 16; kk++) {
            float4 xa = *(const float4*)&Xs[kk][tm * 8];
            float4 xb = *(const float4*)&Xs[kk][tm * 8 + 4];
            float4 kw = *(const float4*)&Ks[kk][tn * 4];
            float4 vw = *(const float4*)&Vs[kk][tn * 4];
            float xv[8] = {xa.x, xa.y, xa.z, xa.w, xb.x, xb.y, xb.z, xb.w};
            float kwv[4] = {kw.x, kw.y, kw.z, kw.w};
            float vwv[4] = {vw.x, vw.y, vw.z, vw.w};
            #pragma unroll
            for (int i = 0; i < 8; i++)
                #pragma unroll
                for (int j = 0; j < 4; j++) {
                    accK[i][j] = fmaf(xv[i], kwv[j], accK[i][j]);
                    accV[i][j] = fmaf(xv[i], vwv[j], accV[i][j]);
                }
        }
        __syncthreads();
    }
    #pragma unroll
    for (int j = 0; j < 4; j++) {
        int n = n0 + tn * 4 + j, h = n >> 6, d = n & 63;
        float bkv = bk[n], bvv = bv[n];
        #pragma unroll
        for (int i = 0; i < 8; i++) {
            int m = m0 + tm * 8 + i;
            g_kt[(((size_t)b * NH + h) * DK + d) * MEM_ + m] = accK[i][j] + bkv;
            g_vp[(((size_t)b * NH + h) * MEM_ + m) * DK + d] = accV[i][j] + bvv;
        }
    }
}

extern __shared__ __align__(128) float dynf[];

__device__ __forceinline__ void grid_bar() {
    __syncthreads();
    if (threadIdx.x == 0) {
        unsigned gen = g_bar_gen;
        __threadfence();
        unsigned ticket = atomicAdd(&g_bar_count, 1u);
        if (ticket == gridDim.x - 1) { g_bar_count = 0; __threadfence(); g_bar_gen = gen + 1; }
        else { while (g_bar_gen == gen) __nanosleep(32); __threadfence(); }
    }
    __syncthreads();
}

__global__ void __launch_bounds__(512, 1) decode_kernel(
    const float* __restrict__ emb,  const float* __restrict__ Wq,  const float* __restrict__ bq,
    const float* __restrict__ Wih,  const float* __restrict__ Whh,
    const float* __restrict__ bih,  const float* __restrict__ bhh,
    const float* __restrict__ Wfc,  const float* __restrict__ bfc,
    const int*   __restrict__ lens, float* __restrict__ out)
{
    const int bid = blockIdx.x, tid = threadIdx.x;
    const int wrp = tid >> 5, lane = tid & 31;
    const int n0q = bid * 4, j0 = bid * 4, n0f = bid * 8;
    const unsigned mb = s2u(&dynf[MBF]);
    const unsigned ring_s = s2u(&dynf[RING]);

    // resident weights: Wq h-part (cols 512..1023), Wih rows, Whh rows, Wfc
    for (int i = tid; i < 4 * 512; i += 512)
        dynf[RWQ + i] = Wq[(size_t)(n0q + (i >> 9)) * (2 * H_) + 512 + (i & 511)];
    for (int i = tid; i < 24 * 512; i += 512) {
        int r24 = i >> 9, k = i & 511, p = r24 / 12, r = r24 % 12, g = r >> 2, jj = r & 3;
        dynf[RWG + i] = (p ? Whh : Wih)[(size_t)(g * H_ + j0 + jj) * H_ + k];
    }
    if (bid < NFC)
        for (int i = tid; i < 8 * 512; i += 512)
            dynf[RWF + i] = Wfc[(size_t)(n0f + (i >> 9)) * H_ + (i & 511)];
    if (tid == 0) { mbar_init(mb, 1u); mbar_init(mb + 8, 1u); mbar_init(mb + 16, 1u); }
    __syncthreads();
    int p0 = 0, p1 = 0, p2 = 0;

    for (int t = 0; t < TMAX; t++) {
        const float* hcur = g_h2[t & 1];
        float* hnext = g_h2[(t + 1) & 1];
        float ghreg[3] = {0.f, 0.f, 0.f};   // Whh@h for (jj=tid>>7, b=tid&127)

        // ========== Q: toks, q = qe[tok] + Wq_h@h, and gh = Whh@h (hoisted) ====
        {
            int* TOK = (int*)&dynf[QTOK];
            if (t == 0) { if (tid < BS) TOK[tid] = 0; }
            else {
                float* AV = &dynf[QAV]; int* AI = (int*)&dynf[QAI];
                int l = tid >> 7, b = tid & 127;
                float bv = -3.4e38f; int bi = 0;
                for (int p = l; p < NFC; p += 4) {
                    float v = g_pv[p * BS + b]; int ix = g_pi[p * BS + b];
                    if (v > bv || (v == bv && ix < bi)) { bv = v; bi = ix; }
                }
                AV[l * 128 + b] = bv; AI[l * 128 + b] = bi;
                __syncthreads();
                if (tid < BS) {
                    float cv = AV[tid]; int ci = AI[tid];
                    #pragma unroll
                    for (int l2 = 1; l2 < 4; l2++) {
                        float v = AV[l2 * 128 + tid]; int ix = AI[l2 * 128 + tid];
                        if (v > cv || (v == cv && ix < ci)) { cv = v; ci = ix; }
                    }
                    TOK[tid] = ci;
                }
            }
            __syncthreads();
            const int gb = tid & 127, gjj = tid >> 7;
            float acc[4][8] = {};
            for (int c = 0; c < 4; c++) {
                #pragma unroll
                for (int i = 0; i < 8; i++) {
                    int e = tid + i * 512, b = e >> 5, k4 = e & 31;
                    *(float4*)&dynf[QX + b * 132 + k4 * 4] =
                        *(const float4*)(hcur + b * H_ + c * 128 + k4 * 4);
                }
                __syncthreads();
                #pragma unroll
                for (int j = 0; j < 4; j++) {
                    int kk = lane + 32 * j;
                    float wv[4];
                    #pragma unroll
                    for (int ni = 0; ni < 4; ni++) wv[ni] = dynf[RWQ + ni * 512 + c * 128 + kk];
                    #pragma unroll
                    for (int bi = 0; bi < 8; bi++) {
                        float x = dynf[QX + (wrp * 8 + bi) * 132 + kk];
                        #pragma unroll
                        for (int ni = 0; ni < 4; ni++) acc[ni][bi] = fmaf(x, wv[ni], acc[ni][bi]);
                    }
                }
                // gh partial for this 128-k window (same staged h)
                #pragma unroll 8
                for (int kk = 0; kk < 128; kk++) {
                    float x = dynf[QX + gb * 132 + kk];
                    #pragma unroll
                    for (int g = 0; g < 3; g++)
                        ghreg[g] = fmaf(x, dynf[RWG + (12 + g * 4 + gjj) * 512 + c * 128 + kk], ghreg[g]);
                }
                __syncthreads();
            }
            #pragma unroll
            for (int j = 0; j < 32; j++) {
                int ni = j >> 3, bi = j & 7;
                float v = acc[ni][bi];
                #pragma unroll
                for (int o = 16; o > 0; o >>= 1) v += __shfl_xor_sync(0xffffffffu, v, o);
                if (lane == j) {
                    int n = n0q + ni, b = wrp * 8 + bi;
                    g_q[b * D_ + n] = v + bq[n] + g_qe[(size_t)((int*)&dynf[QTOK])[b] * D_ + n];
                }
            }
        }
        grid_bar();

        // ========== ATT: unified 64-chunk TMA stream (32 K + 32 V) ==========
        {
            dynf[A_QS + tid] = g_q[bid * D_ + tid];
            __syncthreads();
            const float* ksrc = g_kt + (size_t)bid * NH * DK * MEM_;
            const float* vsrc = g_vp + (size_t)bid * NH * MEM_ * DK;
            if (tid == 0) {
                fence_pa();
                #pragma unroll
                for (int j = 0; j < 3; j++) {
                    mbar_expect_tx(mb + 8u * j, 32768);
                    tma_g2s(ring_s + j * 32768, ksrc + (size_t)j * 8192, 32768, mb + 8u * j);
                }
            }
            float acc = 0.f, accv = 0.f;
            const int vg = tid >> 6, vd = tid & 63;
            for (int c = 0; c < 64; c++) {
                int jb = c % 3, pj;
                if (jb == 0) { pj = p0; p0 ^= 1; }
                else if (jb == 1) { pj = p1; p1 ^= 1; }
                else { pj = p2; p2 ^= 1; }
                mbar_wait(mb + 8u * jb, pj);
                const float* Bf = &dynf[RING + jb * 8192];
                if (c < 32) {
                    int h = c >> 2, d0 = (c & 3) * 16;
                    if (d0 == 0) acc = 0.f;
                    #pragma unroll
                    for (int u = 0; u < 16; u++)
                        acc = fmaf(dynf[A_QS + h * DK + d0 + u], Bf[u * MEM_ + tid], acc);
                    if (d0 == 48) dynf[A_SC + h * MEM_ + tid] = acc * 0.125f;
                } else {
                    int cv = c - 32, vh = cv >> 2, m0 = (cv & 3) * 128;
                    if (m0 == 0) accv = 0.f;
                    const float* ph = &dynf[A_SC + vh * MEM_ + m0];
                    #pragma unroll
                    for (int u = 0; u < 16; u++) {
                        int ml = vg * 16 + u;
                        accv = fmaf(ph[ml], Bf[ml * 64 + vd], accv);
                    }
                    if (m0 == 384) dynf[A_RED + (vh * 8 + vg) * 64 + vd] = accv;
                }
                __syncthreads();
                if (c == 31) {
                    int h = tid >> 6, i = tid & 63;
                    float mx = -3.4e38f;
                    #pragma unroll
                    for (int r = 0; r < 8; r++) mx = fmaxf(mx, dynf[A_SC + h * MEM_ + i + (r << 6)]);
                    #pragma unroll
                    for (int o = 16; o > 0; o >>= 1) mx = fmaxf(mx, __shfl_xor_sync(0xffffffffu, mx, o));
                    if ((tid & 31) == 0) dynf[A_W1 + (tid >> 5)] = mx;
                    __syncthreads();
                    float mh = fmaxf(dynf[A_W1 + 2 * h], dynf[A_W1 + 2 * h + 1]);
                    float s = 0.f;
                    #pragma unroll
                    for (int r = 0; r < 8; r++) {
                        int m = i + (r << 6);
                        float e = expf(dynf[A_SC + h * MEM_ + m] - mh);
                        dynf[A_SC + h * MEM_ + m] = e;
                        s += e;
                    }
                    #pragma unroll
                    for (int o = 16; o > 0; o >>= 1) s += __shfl_xor_sync(0xffffffffu, s, o);
                    if ((tid & 31) == 0) dynf[A_W2 + (tid >> 5)] = s;
                    __syncthreads();
                    float inv = 1.f / (dynf[A_W2 + 2 * h] + dynf[A_W2 + 2 * h + 1]);
                    if (i == 0) dynf[A_INV + h] = inv;
                    __syncthreads();
                    float sm = 0.f;
                    #pragma unroll
                    for (int hh = 0; hh < NH; hh++)
                        sm += dynf[A_SC + hh * MEM_ + tid] * dynf[A_INV + hh];
                    sm *= 0.125f;
                    int run = t < lens[bid];
                    out[OUT_S_OFF + ((size_t)t * BS + bid) * MEM_ + tid] = run ? sm : 0.f;
                }
                if (tid == 0 && c + 3 < 64) {
                    int nc = c + 3, j2 = nc % 3;
                    const float* src = (nc < 32) ? (ksrc + (size_t)nc * 8192)
                                                 : (vsrc + (size_t)(nc - 32) * 8192);
                    mbar_expect_tx(mb + 8u * j2, 32768);
                    tma_g2s(ring_s + j2 * 32768, src, 32768, mb + 8u * j2);
                }
            }
            int rh = tid >> 6, rd = tid & 63;
            float sum = 0.f;
            #pragma unroll
            for (int gg = 0; gg < 8; gg++) sum += dynf[A_RED + (rh * 8 + gg) * 64 + rd];
            g_ctx[bid * D_ + rh * DK + rd] = sum * dynf[A_INV + rh];
        }
        grid_bar();

        // ========== GRU: gi = Wih@ctx (16-way k-split) + fused activation ======
        {
            const int ks = wrp;
            float ag[12][4] = {};
            for (int c = 0; c < 8; c++) {
                #pragma unroll
                for (int i = 0; i < 8; i++) {
                    int e = tid + i * 512;
                    int r = e >> 5, k2 = e & 31;
                    float2 v = *(const float2*)(g_ctx + r * 512 + c * 64 + k2 * 2);
                    *(float2*)&dynf[GX + r * 64 + ((k2 * 2) ^ ((r & 15) << 1))] = v;
                }
                __syncthreads();
                #pragma unroll
                for (int uu = 0; uu < 4; uu++) {
                    int kk = ks * 4 + uu;
                    int kg = c * 64 + kk;
                    float xv[4];
                    #pragma unroll
                    for (int bi = 0; bi < 4; bi++) {
                        int b = lane + bi * 32;
                        xv[bi] = dynf[GX + b * 64 + (kk ^ ((b & 15) << 1))];
                    }
                    #pragma unroll
                    for (int row = 0; row < 12; row++) {
                        float wv = dynf[RWG + row * 512 + kg];
                        #pragma unroll
                        for (int bi = 0; bi < 4; bi++) ag[row][bi] = fmaf(xv[bi], wv, ag[row][bi]);
                    }
                }
                __syncthreads();
            }
            #pragma unroll
            for (int row = 0; row < 12; row++)
                #pragma unroll
                for (int bi = 0; bi < 4; bi++)
                    dynf[GP + (ks * 12 + row) * 128 + lane + bi * 32] = ag[row][bi];
            __syncthreads();
            {
                int b = tid & 127, jj = tid >> 7, j = j0 + jj;
                float gi[3];
                #pragma unroll
                for (int g = 0; g < 3; g++) {
                    float s0 = 0.f;
                    #pragma unroll
                    for (int k2 = 0; k2 < 16; k2++)
                        s0 += dynf[GP + (k2 * 12 + g * 4 + jj) * 128 + b];
                    gi[g] = s0 + bih[g * H_ + j];
                }
                float ghr = ghreg[0] + bhh[j];
                float ghz = ghreg[1] + bhh[H_ + j];
                float ghn = ghreg[2] + bhh[2 * H_ + j];
                float rr = sigmoidf_(gi[0] + ghr);
                float zz = sigmoidf_(gi[1] + ghz);
                float nn = tanhf(gi[2] + rr * ghn);
                float hold = hcur[b * H_ + j];
                float hn = (1.f - zz) * nn + zz * hold;
                hnext[b * H_ + j] = hn;
                int run = t < lens[b];
                out[OUT_H_OFF + ((size_t)t * BS + b) * H_ + j] = run ? hn : 0.f;
            }
        }
        grid_bar();

        // ========== FC + partial argmax ==========
        if (bid < NFC) {
            float af[8][8] = {};
            for (int c = 0; c < 4; c++) {
                #pragma unroll
                for (int i = 0; i < 8; i++) {
                    int e = tid + i * 512, b = e >> 5, k4 = e & 31;
                    *(float4*)&dynf[FX + b * 132 + k4 * 4] =
                        *(const float4*)(hnext + b * H_ + c * 128 + k4 * 4);
                }
                __syncthreads();
                #pragma unroll
                for (int j = 0; j < 4; j++) {
                    int kk = lane + 32 * j;
                    float wv[8];
                    #pragma unroll
                    for (int ni = 0; ni < 8; ni++) wv[ni] = dynf[RWF + ni * 512 + c * 128 + kk];
                    #pragma unroll
                    for (int bi = 0; bi < 8; bi++) {
                        float x = dynf[FX + (wrp * 8 + bi) * 132 + kk];
                        #pragma unroll
                        for (int ni = 0; ni < 8; ni++) af[ni][bi] = fmaf(x, wv[ni], af[ni][bi]);
                    }
                }
                __syncthreads();
            }
            float rr0 = 0.f, rr1 = 0.f;
            #pragma unroll
            for (int j = 0; j < 64; j++) {
                int ni = j >> 3, bi = j & 7;
                float v = af[ni][bi];
                #pragma unroll
                for (int o = 16; o > 0; o >>= 1) v += __shfl_xor_sync(0xffffffffu, v, o);
                if (lane == (j & 31)) { if (j < 32) rr0 = v; else rr1 = v; }
            }
            int bi = lane & 7, b = wrp * 8 + bi;
            int nA = n0f + (lane >> 3), nB = nA + 4;
            float vA = rr0 + bfc[nA], vB = rr1 + bfc[nB];
            int run = t < lens[b];
            size_t ob = ((size_t)t * BS + b) * V_;
            out[ob + nA] = run ? vA : 0.f;
            out[ob + nB] = run ? vB : 0.f;
            float mv = vA; int mi = nA;
            if (vB > mv) { mv = vB; mi = nB; }
            #pragma unroll
            for (int o = 8; o <= 16; o <<= 1) {
                float v2 = __shfl_xor_sync(0xffffffffu, mv, o);
                int   i2 = __shfl_xor_sync(0xffffffffu, mi, o);
                if (v2 > mv || (v2 == mv && i2 < mi)) { mv = v2; mi = i2; }
            }
            if (lane < 8) { g_pv[bid * BS + b] = mv; g_pi[bid * BS + b] = mi; }
        }
        grid_bar();
    }
}

extern "C" void kernel_launch(void* const* d_in, const int* in_sizes, int n_in,
                              void* d_out, int out_size)
{
    const float* memory = (const float*)d_in[0];
    const float* emb    = (const float*)d_in[1];
    const float* Wq     = (const float*)d_in[2];
    const float* bq     = (const float*)d_in[3];
    const float* Wk     = (const float*)d_in[4];
    const float* bk     = (const float*)d_in[5];
    const float* Wv     = (const float*)d_in[6];
    const float* bv     = (const float*)d_in[7];
    const float* Wih    = (const float*)d_in[8];
    const float* Whh    = (const float*)d_in[9];
    const float* bih    = (const float*)d_in[10];
    const float* bhh    = (const float*)d_in[11];
    const float* Wfc    = (const float*)d_in[12];
    const float* bfc    = (const float*)d_in[13];
    const int*   lens   = (const int*)d_in[14];
    float* out = (float*)d_out;

    cudaFuncSetAttribute(decode_kernel, cudaFuncAttributeMaxDynamicSharedMemorySize, SMEM_BYTES);

    init_kernel<<<128, 256>>>();
    qe_kernel<<<dim3(16, 8), 256>>>(emb, Wq);
    kvproj_kernel<<<dim3(MEM_ / 128, D_ / 64, BS), 256>>>(memory, Wk, bk, Wv, bv);
    decode_kernel<<<NBLK, 512, SMEM_BYTES>>>(emb, Wq, bq, Wih, Whh, bih, bhh, Wfc, bfc, lens, out);
}

// round 15
// speedup vs baseline: 1.8940x; 1.0061x over previous
#include <cuda_runtime.h>
#include <math.h>
#include <stdint.h>

#define V_   1000
#define H_   512
#define D_   512
#define NH   8
#define DK   64
#define MEM_ 512
#define BS   128
#define TMAX 160
#define NBLK 128
#define NFC  125
#define NKEEP 50            // blocks whose K/V pins L2 (50*2MB = 100MB < 126MB)

#define OUT_H_OFF (TMAX*BS*V_)
#define OUT_S_OFF (OUT_H_OFF + TMAX*BS*H_)

// ---- dynamic smem layout (float indices) ----
#define A_QS   0
#define A_SC   512
#define A_RED  4608
#define A_W1   8704
#define A_W2   8720
#define A_INV  8736
#define RING   8768
#define QX     0
#define QTOK   16896
#define QAV    17024
#define QAI    17536
#define GX     0
#define GP     0
#define FX     0
#define RWQ    33376
#define RWG    37472
#define RWF    49760
#define MBF    53856
#define SMEM_BYTES (53864*4)

__device__ float g_kt[(size_t)BS*NH*DK*MEM_];
__device__ float g_vp[(size_t)BS*NH*MEM_*DK];
__device__ float g_qe[(size_t)V_*D_];
__device__ float g_h2[2][BS*H_];
__device__ float g_q [BS*D_];
__device__ float g_ctx[BS*D_];
__device__ float g_pv[NFC*BS];
__device__ int   g_pi[NFC*BS];
__device__ unsigned g_bar_count;
__device__ volatile unsigned g_bar_gen;

__device__ __forceinline__ unsigned s2u(const void* p) {
    return (unsigned)__cvta_generic_to_shared(p);
}
__device__ __forceinline__ void mbar_init(unsigned a, unsigned cnt) {
    asm volatile("mbarrier.init.shared.b64 [%0], %1;" :: "r"(a), "r"(cnt) : "memory");
}
__device__ __forceinline__ void mbar_expect_tx(unsigned a, unsigned bytes) {
    asm volatile("mbarrier.arrive.expect_tx.shared.b64 _, [%0], %1;" :: "r"(a), "r"(bytes) : "memory");
}
__device__ __forceinline__ void mbar_wait(unsigned a, unsigned parity) {
    unsigned done;
    asm volatile("{\n\t.reg .pred p;\n\t"
        "mbarrier.try_wait.parity.acquire.cta.shared::cta.b64 p, [%1], %2, 0x989680;\n\t"
        "selp.b32 %0, 1, 0, p;\n\t}" : "=r"(done) : "r"(a), "r"(parity) : "memory");
    while (!done) {
        asm volatile("{\n\t.reg .pred p;\n\t"
            "mbarrier.try_wait.parity.acquire.cta.shared::cta.b64 p, [%1], %2, 0x989680;\n\t"
            "selp.b32 %0, 1, 0, p;\n\t}" : "=r"(done) : "r"(a), "r"(parity) : "memory");
    }
}
__device__ __forceinline__ void tma_g2s_pol(unsigned dst, const void* src, unsigned bytes,
                                            unsigned mbar, uint64_t pol) {
    asm volatile(
        "cp.async.bulk.shared::cluster.global.mbarrier::complete_tx::bytes.L2::cache_hint"
        " [%0], [%1], %2, [%3], %4;"
        :: "r"(dst), "l"(src), "r"(bytes), "r"(mbar), "l"(pol) : "memory");
}
__device__ __forceinline__ void fence_pa() {
    asm volatile("fence.proxy.async.shared::cta;" ::: "memory");
}
__device__ __forceinline__ float sigmoidf_(float x) { return 1.f / (1.f + expf(-x)); }

__global__ void init_kernel() {
    int i = blockIdx.x * blockDim.x + threadIdx.x;
    for (; i < 2 * BS * H_; i += gridDim.x * blockDim.x) ((float*)g_h2)[i] = 0.f;
}

// ---- qe = emb @ Wq[:, :512]^T (once) ----
__global__ void __launch_bounds__(256) qe_kernel(const float* __restrict__ emb,
                                                 const float* __restrict__ Wq)
{
    __shared__ float Es[16][68], Qs[16][68];
    int v0 = blockIdx.x * 64, n0 = blockIdx.y * 64;
    int tid = threadIdx.x, tn = tid & 15, tm = tid >> 4;
    float acc[4][4] = {};
    for (int k0 = 0; k0 < 512; k0 += 16) {
        #pragma unroll
        for (int i = 0; i < 4; i++) {
            int e = tid + i * 256, kk = e & 15, mm = e >> 4;
            int v = v0 + mm;
            Es[kk][mm] = (v < V_) ? emb[(size_t)v * H_ + k0 + kk] : 0.f;
            Qs[kk][mm] = Wq[(size_t)(n0 + mm) * (2 * H_) + k0 + kk];
        }
        __syncthreads();
        #pragma unroll
        for (int kk = 0; kk < 16; kk++) {
            float4 xa = *(const float4*)&Es[kk][tm * 4];
            float4 wa = *(const float4*)&Qs[kk][tn * 4];
            float xv[4] = {xa.x, xa.y, xa.z, xa.w};
            float wv[4] = {wa.x, wa.y, wa.z, wa.w};
            #pragma unroll
            for (int i = 0; i < 4; i++)
                #pragma unroll
                for (int j = 0; j < 4; j++)
                    acc[i][j] = fmaf(xv[i], wv[j], acc[i][j]);
        }
        __syncthreads();
    }
    #pragma unroll
    for (int i = 0; i < 4; i++) {
        int v = v0 + tm * 4 + i;
        if (v < V_)
            #pragma unroll
            for (int j = 0; j < 4; j++)
                g_qe[(size_t)v * D_ + n0 + tn * 4 + j] = acc[i][j];
    }
}

// ---- KV projection ----
__global__ void __launch_bounds__(256) kvproj_kernel(
    const float* __restrict__ memory, const float* __restrict__ Wk, const float* __restrict__ bk,
    const float* __restrict__ Wv, const float* __restrict__ bv)
{
    __shared__ float Xs[16][132];
    __shared__ float Ks[16][68];
    __shared__ float Vs[16][68];
    const int m0 = blockIdx.x * 128, n0 = blockIdx.y * 64, b = blockIdx.z;
    const int tid = threadIdx.x, tn = tid & 15, tm = tid >> 4;
    float accK[8][4] = {}, accV[8][4] = {};

    for (int k0 = 0; k0 < D_; k0 += 16) {
        #pragma unroll
        for (int i = 0; i < 8; i++) {
            int e = tid + i * 256, kk = e & 15, mm = e >> 4;
            Xs[kk][mm] = memory[((size_t)(m0 + mm) * BS + b) * D_ + k0 + kk];
        }
        #pragma unroll
        for (int i = 0; i < 4; i++) {
            int e = tid + i * 256, kk = e & 15, nn = e >> 4;
            Ks[kk][nn] = Wk[(size_t)(n0 + nn) * D_ + k0 + kk];
            Vs[kk][nn] = Wv[(size_t)(n0 + nn) * D_ + k0 + kk];
        }
        __syncthreads();
        #pragma unroll
        for (int kk = 0; kk < 16; kk++) {
            float4 xa = *(const float4*)&Xs[kk][tm * 8];
            float4 xb = *(const float4*)&Xs[kk][tm * 8 + 4];
            float4 kw = *(const float4*)&Ks[kk][tn * 4];
            float4 vw = *(const float4*)&Vs[kk][tn * 4];
            float xv[8] = {xa.x, xa.y, xa.z, xa.w, xb.x, xb.y, xb.z, xb.w};
            float kwv[4] = {kw.x, kw.y, kw.z, kw.w};
            float vwv[4] = {vw.x, vw.y, vw.z, vw.w};
            #pragma unroll
            for (int i = 0; i < 8; i++)
                #pragma unroll
                for (int j = 0; j < 4; j++) {
                    accK[i][j] = fmaf(xv[i], kwv[j], accK[i][j]);
                    accV[i][j] = fmaf(xv[i], vwv[j], accV[i][j]);
                }
        }
        __syncthreads();
    }
    #pragma unroll
    for (int j = 0; j < 4; j++) {
        int n = n0 + tn * 4 + j, h = n >> 6, d = n & 63;
        float bkv = bk[n], bvv = bv[n];
        #pragma unroll
        for (int i = 0; i < 8; i++) {
            int m = m0 + tm * 8 + i;
            g_kt[(((size_t)b * NH + h) * DK + d) * MEM_ + m] = accK[i][j] + bkv;
            g_vp[(((size_t)b * NH + h) * MEM_ + m) * DK + d] = accV[i][j] + bvv;
        }
    }
}

extern __shared__ __align__(128) float dynf[];

__device__ __forceinline__ void grid_bar() {
    __syncthreads();
    if (threadIdx.x == 0) {
        unsigned gen = g_bar_gen;
        __threadfence();
        unsigned ticket = atomicAdd(&g_bar_count, 1u);
        if (ticket == gridDim.x - 1) { g_bar_count = 0; __threadfence(); g_bar_gen = gen + 1; }
        else { while (g_bar_gen == gen) __nanosleep(32); __threadfence(); }
    }
    __syncthreads();
}

__global__ void __launch_bounds__(512, 1) decode_kernel(
    const float* __restrict__ emb,  const float* __restrict__ Wq,  const float* __restrict__ bq,
    const float* __restrict__ Wih,  const float* __restrict__ Whh,
    const float* __restrict__ bih,  const float* __restrict__ bhh,
    const float* __restrict__ Wfc,  const float* __restrict__ bfc,
    const int*   __restrict__ lens, float* __restrict__ out)
{
    const int bid = blockIdx.x, tid = threadIdx.x;
    const int wrp = tid >> 5, lane = tid & 31;
    const int n0q = bid * 4, j0 = bid * 4, n0f = bid * 8;
    const unsigned mb = s2u(&dynf[MBF]);
    const unsigned ring_s = s2u(&dynf[RING]);

    // L2 cache policy: first NKEEP blocks pin their K/V resident, rest stream
    uint64_t l2pol;
    if (bid < NKEEP)
        asm volatile("createpolicy.fractional.L2::evict_last.b64 %0, 1.0;" : "=l"(l2pol));
    else
        asm volatile("createpolicy.fractional.L2::evict_first.b64 %0, 1.0;" : "=l"(l2pol));

    // resident weights: Wq h-part, Wih+Whh rows, Wfc
    for (int i = tid; i < 4 * 512; i += 512)
        dynf[RWQ + i] = Wq[(size_t)(n0q + (i >> 9)) * (2 * H_) + 512 + (i & 511)];
    for (int i = tid; i < 24 * 512; i += 512) {
        int r24 = i >> 9, k = i & 511, p = r24 / 12, r = r24 % 12, g = r >> 2, jj = r & 3;
        dynf[RWG + i] = (p ? Whh : Wih)[(size_t)(g * H_ + j0 + jj) * H_ + k];
    }
    if (bid < NFC)
        for (int i = tid; i < 8 * 512; i += 512)
            dynf[RWF + i] = Wfc[(size_t)(n0f + (i >> 9)) * H_ + (i & 511)];
    if (tid == 0) { mbar_init(mb, 1u); mbar_init(mb + 8, 1u); mbar_init(mb + 16, 1u); }
    __syncthreads();
    int p0 = 0, p1 = 0, p2 = 0;

    for (int t = 0; t < TMAX; t++) {
        const float* hcur = g_h2[t & 1];
        float* hnext = g_h2[(t + 1) & 1];
        float ghreg[3] = {0.f, 0.f, 0.f};

        // ========== Q: toks, q = qe[tok] + Wq_h@h, gh = Whh@h (hoisted) ==========
        {
            int* TOK = (int*)&dynf[QTOK];
            if (t == 0) { if (tid < BS) TOK[tid] = 0; }
            else {
                float* AV = &dynf[QAV]; int* AI = (int*)&dynf[QAI];
                int l = tid >> 7, b = tid & 127;
                float bv = -3.4e38f; int bi = 0;
                for (int p = l; p < NFC; p += 4) {
                    float v = g_pv[p * BS + b]; int ix = g_pi[p * BS + b];
                    if (v > bv || (v == bv && ix < bi)) { bv = v; bi = ix; }
                }
                AV[l * 128 + b] = bv; AI[l * 128 + b] = bi;
                __syncthreads();
                if (tid < BS) {
                    float cv = AV[tid]; int ci = AI[tid];
                    #pragma unroll
                    for (int l2 = 1; l2 < 4; l2++) {
                        float v = AV[l2 * 128 + tid]; int ix = AI[l2 * 128 + tid];
                        if (v > cv || (v == cv && ix < ci)) { cv = v; ci = ix; }
                    }
                    TOK[tid] = ci;
                }
            }
            __syncthreads();
            const int gb = tid & 127, gjj = tid >> 7;
            float acc[4][8] = {};
            for (int c = 0; c < 4; c++) {
                #pragma unroll
                for (int i = 0; i < 8; i++) {
                    int e = tid + i * 512, b = e >> 5, k4 = e & 31;
                    *(float4*)&dynf[QX + b * 132 + k4 * 4] =
                        *(const float4*)(hcur + b * H_ + c * 128 + k4 * 4);
                }
                __syncthreads();
                #pragma unroll
                for (int j = 0; j < 4; j++) {
                    int kk = lane + 32 * j;
                    float wv[4];
                    #pragma unroll
                    for (int ni = 0; ni < 4; ni++) wv[ni] = dynf[RWQ + ni * 512 + c * 128 + kk];
                    #pragma unroll
                    for (int bi = 0; bi < 8; bi++) {
                        float x = dynf[QX + (wrp * 8 + bi) * 132 + kk];
                        #pragma unroll
                        for (int ni = 0; ni < 4; ni++) acc[ni][bi] = fmaf(x, wv[ni], acc[ni][bi]);
                    }
                }
                // gh partial: float4 x and broadcast float4 weights
                #pragma unroll
                for (int kk4 = 0; kk4 < 32; kk4++) {
                    float4 x4 = *(const float4*)&dynf[QX + gb * 132 + kk4 * 4];
                    #pragma unroll
                    for (int g = 0; g < 3; g++) {
                        float4 w4 = *(const float4*)&dynf[RWG + (12 + g * 4 + gjj) * 512 + c * 128 + kk4 * 4];
                        ghreg[g] = fmaf(x4.x, w4.x, ghreg[g]);
                        ghreg[g] = fmaf(x4.y, w4.y, ghreg[g]);
                        ghreg[g] = fmaf(x4.z, w4.z, ghreg[g]);
                        ghreg[g] = fmaf(x4.w, w4.w, ghreg[g]);
                    }
                }
                __syncthreads();
            }
            #pragma unroll
            for (int j = 0; j < 32; j++) {
                int ni = j >> 3, bi = j & 7;
                float v = acc[ni][bi];
                #pragma unroll
                for (int o = 16; o > 0; o >>= 1) v += __shfl_xor_sync(0xffffffffu, v, o);
                if (lane == j) {
                    int n = n0q + ni, b = wrp * 8 + bi;
                    g_q[b * D_ + n] = v + bq[n] + g_qe[(size_t)((int*)&dynf[QTOK])[b] * D_ + n];
                }
            }
        }
        grid_bar();

        // ========== ATT: unified 64-chunk TMA stream (32 K + 32 V) ==========
        {
            dynf[A_QS + tid] = g_q[bid * D_ + tid];
            __syncthreads();
            const float* ksrc = g_kt + (size_t)bid * NH * DK * MEM_;
            const float* vsrc = g_vp + (size_t)bid * NH * MEM_ * DK;
            if (tid == 0) {
                fence_pa();
                #pragma unroll
                for (int j = 0; j < 3; j++) {
                    mbar_expect_tx(mb + 8u * j, 32768);
                    tma_g2s_pol(ring_s + j * 32768, ksrc + (size_t)j * 8192, 32768, mb + 8u * j, l2pol);
                }
            }
            float acc = 0.f, accv = 0.f;
            const int vg = tid >> 6, vd = tid & 63;
            for (int c = 0; c < 64; c++) {
                int jb = c % 3, pj;
                if (jb == 0) { pj = p0; p0 ^= 1; }
                else if (jb == 1) { pj = p1; p1 ^= 1; }
                else { pj = p2; p2 ^= 1; }
                mbar_wait(mb + 8u * jb, pj);
                const float* Bf = &dynf[RING + jb * 8192];
                if (c < 32) {
                    int h = c >> 2, d0 = (c & 3) * 16;
                    if (d0 == 0) acc = 0.f;
                    #pragma unroll
                    for (int u = 0; u < 16; u++)
                        acc = fmaf(dynf[A_QS + h * DK + d0 + u], Bf[u * MEM_ + tid], acc);
                    if (d0 == 48) dynf[A_SC + h * MEM_ + tid] = acc * 0.125f;
                } else {
                    int cv = c - 32, vh = cv >> 2, m0 = (cv & 3) * 128;
                    if (m0 == 0) accv = 0.f;
                    const float* ph = &dynf[A_SC + vh * MEM_ + m0];
                    #pragma unroll
                    for (int u = 0; u < 16; u++) {
                        int ml = vg * 16 + u;
                        accv = fmaf(ph[ml], Bf[ml * 64 + vd], accv);
                    }
                    if (m0 == 384) dynf[A_RED + (vh * 8 + vg) * 64 + vd] = accv;
                }
                __syncthreads();
                if (c == 31) {
                    int h = tid >> 6, i = tid & 63;
                    float mx = -3.4e38f;
                    #pragma unroll
                    for (int r = 0; r < 8; r++) mx = fmaxf(mx, dynf[A_SC + h * MEM_ + i + (r << 6)]);
                    #pragma unroll
                    for (int o = 16; o > 0; o >>= 1) mx = fmaxf(mx, __shfl_xor_sync(0xffffffffu, mx, o));
                    if ((tid & 31) == 0) dynf[A_W1 + (tid >> 5)] = mx;
                    __syncthreads();
                    float mh = fmaxf(dynf[A_W1 + 2 * h], dynf[A_W1 + 2 * h + 1]);
                    float s = 0.f;
                    #pragma unroll
                    for (int r = 0; r < 8; r++) {
                        int m = i + (r << 6);
                        float e = expf(dynf[A_SC + h * MEM_ + m] - mh);
                        dynf[A_SC + h * MEM_ + m] = e;
                        s += e;
                    }
                    #pragma unroll
                    for (int o = 16; o > 0; o >>= 1) s += __shfl_xor_sync(0xffffffffu, s, o);
                    if ((tid & 31) == 0) dynf[A_W2 + (tid >> 5)] = s;
                    __syncthreads();
                    float inv = 1.f / (dynf[A_W2 + 2 * h] + dynf[A_W2 + 2 * h + 1]);
                    if (i == 0) dynf[A_INV + h] = inv;
                    __syncthreads();
                    float sm = 0.f;
                    #pragma unroll
                    for (int hh = 0; hh < NH; hh++)
                        sm += dynf[A_SC + hh * MEM_ + tid] * dynf[A_INV + hh];
                    sm *= 0.125f;
                    int run = t < lens[bid];
                    out[OUT_S_OFF + ((size_t)t * BS + bid) * MEM_ + tid] = run ? sm : 0.f;
                }
                if (tid == 0 && c + 3 < 64) {
                    int nc = c + 3, j2 = nc % 3;
                    const float* src = (nc < 32) ? (ksrc + (size_t)nc * 8192)
                                                 : (vsrc + (size_t)(nc - 32) * 8192);
                    mbar_expect_tx(mb + 8u * j2, 32768);
                    tma_g2s_pol(ring_s + j2 * 32768, src, 32768, mb + 8u * j2, l2pol);
                }
            }
            int rh = tid >> 6, rd = tid & 63;
            float sum = 0.f;
            #pragma unroll
            for (int gg = 0; gg < 8; gg++) sum += dynf[A_RED + (rh * 8 + gg) * 64 + rd];
            g_ctx[bid * D_ + rh * DK + rd] = sum * dynf[A_INV + rh];
        }
        grid_bar();

        // ========== GRU: gi = Wih@ctx (16-way k-split) + fused activation ======
        {
            const int ks = wrp;
            float ag[12][4] = {};
            for (int c = 0; c < 8; c++) {
                #pragma unroll
                for (int i = 0; i < 8; i++) {
                    int e = tid + i * 512;
                    int r = e >> 5, k2 = e & 31;
                    float2 v = *(const float2*)(g_ctx + r * 512 + c * 64 + k2 * 2);
                    *(float2*)&dynf[GX + r * 64 + ((k2 * 2) ^ ((r & 15) << 1))] = v;
                }
                __syncthreads();
                #pragma unroll
                for (int uu = 0; uu < 4; uu++) {
                    int kk = ks * 4 + uu;
                    int kg = c * 64 + kk;
                    float xv[4];
                    #pragma unroll
                    for (int bi = 0; bi < 4; bi++) {
                        int b = lane + bi * 32;
                        xv[bi] = dynf[GX + b * 64 + (kk ^ ((b & 15) << 1))];
                    }
                    #pragma unroll
                    for (int row = 0; row < 12; row++) {
                        float wv = dynf[RWG + row * 512 + kg];
                        #pragma unroll
                        for (int bi = 0; bi < 4; bi++) ag[row][bi] = fmaf(xv[bi], wv, ag[row][bi]);
                    }
                }
                __syncthreads();
            }
            #pragma unroll
            for (int row = 0; row < 12; row++)
                #pragma unroll
                for (int bi = 0; bi < 4; bi++)
                    dynf[GP + (ks * 12 + row) * 128 + lane + bi * 32] = ag[row][bi];
            __syncthreads();
            {
                int b = tid & 127, jj = tid >> 7, j = j0 + jj;
                float gi[3];
                #pragma unroll
                for (int g = 0; g < 3; g++) {
                    float s0 = 0.f;
                    #pragma unroll
                    for (int k2 = 0; k2 < 16; k2++)
                        s0 += dynf[GP + (k2 * 12 + g * 4 + jj) * 128 + b];
                    gi[g] = s0 + bih[g * H_ + j];
                }
                float ghr = ghreg[0] + bhh[j];
                float ghz = ghreg[1] + bhh[H_ + j];
                float ghn = ghreg[2] + bhh[2 * H_ + j];
                float rr = sigmoidf_(gi[0] + ghr);
                float zz = sigmoidf_(gi[1] + ghz);
                float nn = tanhf(gi[2] + rr * ghn);
                float hold = hcur[b * H_ + j];
                float hn = (1.f - zz) * nn + zz * hold;
                hnext[b * H_ + j] = hn;
                int run = t < lens[b];
                out[OUT_H_OFF + ((size_t)t * BS + b) * H_ + j] = run ? hn : 0.f;
            }
        }
        grid_bar();

        // ========== FC + partial argmax ==========
        if (bid < NFC) {
            float af[8][8] = {};
            for (int c = 0; c < 4; c++) {
                #pragma unroll
                for (int i = 0; i < 8; i++) {
                    int e = tid + i * 512, b = e >> 5, k4 = e & 31;
                    *(float4*)&dynf[FX + b * 132 + k4 * 4] =
                        *(const float4*)(hnext + b * H_ + c * 128 + k4 * 4);
                }
                __syncthreads();
                #pragma unroll
                for (int j = 0; j < 4; j++) {
                    int kk = lane + 32 * j;
                    float wv[8];
                    #pragma unroll
                    for (int ni = 0; ni < 8; ni++) wv[ni] = dynf[RWF + ni * 512 + c * 128 + kk];
                    #pragma unroll
                    for (int bi = 0; bi < 8; bi++) {
                        float x = dynf[FX + (wrp * 8 + bi) * 132 + kk];
                        #pragma unroll
                        for (int ni = 0; ni < 8; ni++) af[ni][bi] = fmaf(x, wv[ni], af[ni][bi]);
                    }
                }
                __syncthreads();
            }
            float rr0 = 0.f, rr1 = 0.f;
            #pragma unroll
            for (int j = 0; j < 64; j++) {
                int ni = j >> 3, bi = j & 7;
                float v = af[ni][bi];
                #pragma unroll
                for (int o = 16; o > 0; o >>= 1) v += __shfl_xor_sync(0xffffffffu, v, o);
                if (lane == (j & 31)) { if (j < 32) rr0 = v; else rr1 = v; }
            }
            int bi = lane & 7, b = wrp * 8 + bi;
            int nA = n0f + (lane >> 3), nB = nA + 4;
            float vA = rr0 + bfc[nA], vB = rr1 + bfc[nB];
            int run = t < lens[b];
            size_t ob = ((size_t)t * BS + b) * V_;
            out[ob + nA] = run ? vA : 0.f;
            out[ob + nB] = run ? vB : 0.f;
            float mv = vA; int mi = nA;
            if (vB > mv) { mv = vB; mi = nB; }
            #pragma unroll
            for (int o = 8; o <= 16; o <<= 1) {
                float v2 = __shfl_xor_sync(0xffffffffu, mv, o);
                int   i2 = __shfl_xor_sync(0xffffffffu, mi, o);
                if (v2 > mv || (v2 == mv && i2 < mi)) { mv = v2; mi = i2; }
            }
            if (lane < 8) { g_pv[bid * BS + b] = mv; g_pi[bid * BS + b] = mi; }
        }
        grid_bar();
    }
}

extern "C" void kernel_launch(void* const* d_in, const int* in_sizes, int n_in,
                              void* d_out, int out_size)
{
    const float* memory = (const float*)d_in[0];
    const float* emb    = (const float*)d_in[1];
    const float* Wq     = (const float*)d_in[2];
    const float* bq     = (const float*)d_in[3];
    const float* Wk     = (const float*)d_in[4];
    const float* bk     = (const float*)d_in[5];
    const float* Wv     = (const float*)d_in[6];
    const float* bv     = (const float*)d_in[7];
    const float* Wih    = (const float*)d_in[8];
    const float* Whh    = (const float*)d_in[9];
    const float* bih    = (const float*)d_in[10];
    const float* bhh    = (const float*)d_in[11];
    const float* Wfc    = (const float*)d_in[12];
    const float* bfc    = (const float*)d_in[13];
    const int*   lens   = (const int*)d_in[14];
    float* out = (float*)d_out;

    cudaFuncSetAttribute(decode_kernel, cudaFuncAttributeMaxDynamicSharedMemorySize, SMEM_BYTES);

    init_kernel<<<128, 256>>>();
    qe_kernel<<<dim3(16, 8), 256>>>(emb, Wq);
    kvproj_kernel<<<dim3(MEM_ / 128, D_ / 64, BS), 256>>>(memory, Wk, bk, Wv, bv);
    decode_kernel<<<NBLK, 512, SMEM_BYTES>>>(emb, Wq, bq, Wih, Whh, bih, bhh, Wfc, bfc, lens, out);
}

// round 16
// speedup vs baseline: 1.9627x; 1.0363x over previous
#include <cuda_runtime.h>
#include <math.h>
#include <stdint.h>

#define V_   1000
#define H_   512
#define D_   512
#define NH   8
#define DK   64
#define MEM_ 512
#define BS   128
#define TMAX 160
#define NBLK 128
#define NFC  125
#define NKEEP 50

#define OUT_H_OFF (TMAX*BS*V_)
#define OUT_S_OFF (OUT_H_OFF + TMAX*BS*H_)

// ---- dynamic smem layout (float indices) ----
#define A_QS   0
#define A_SC   512
#define A_RED  4608
#define A_W1   8704
#define A_W2   8720
#define A_INV  8736
#define RING   8768
#define QX     0
#define QTOK   16896
#define QAV    17024
#define QAI    17536
#define GX     0
#define GP     0
#define FX     0
#define RWQ    33376
#define RWG    37472
#define RWF    49760
#define MBF    53856
#define SMEM_BYTES (53864*4)

__device__ __align__(256) float g_kt[(size_t)BS*NH*DK*MEM_];
__device__ __align__(256) float g_vp[(size_t)BS*NH*MEM_*DK];
__device__ float g_qe[(size_t)V_*D_];
__device__ float g_h2[2][BS*H_];
__device__ float g_q [BS*D_];
__device__ float g_ctx[BS*D_];
__device__ float g_pv[NFC*BS];
__device__ int   g_pi[NFC*BS];
__device__ unsigned g_bar_count;
__device__ volatile unsigned g_bar_gen;

// ---- f32x2 packed math ----
#define FMA2(d, a, b) asm("fma.rn.f32x2 %0, %1, %2, %0;" : "+l"(d) : "l"(a), "l"(b))
#define ADD2(d, a, b) asm("add.rn.f32x2 %0, %1, %2;" : "=l"(d) : "l"(a), "l"(b))
#define PACK2(d, lo, hi) asm("mov.b64 %0, {%1, %2};" : "=l"(d) \
    : "r"(__float_as_uint(lo)), "r"(__float_as_uint(hi)))
#define UNPACK2(lo, hi, s) do { unsigned _ulo, _uhi; \
    asm("mov.b64 {%0, %1}, %2;" : "=r"(_ulo), "=r"(_uhi) : "l"(s)); \
    lo = __uint_as_float(_ulo); hi = __uint_as_float(_uhi); } while (0)

__device__ __forceinline__ unsigned s2u(const void* p) {
    return (unsigned)__cvta_generic_to_shared(p);
}
__device__ __forceinline__ void mbar_init(unsigned a, unsigned cnt) {
    asm volatile("mbarrier.init.shared.b64 [%0], %1;" :: "r"(a), "r"(cnt) : "memory");
}
__device__ __forceinline__ void mbar_expect_tx(unsigned a, unsigned bytes) {
    asm volatile("mbarrier.arrive.expect_tx.shared.b64 _, [%0], %1;" :: "r"(a), "r"(bytes) : "memory");
}
__device__ __forceinline__ void mbar_wait(unsigned a, unsigned parity) {
    unsigned done;
    asm volatile("{\n\t.reg .pred p;\n\t"
        "mbarrier.try_wait.parity.acquire.cta.shared::cta.b64 p, [%1], %2, 0x989680;\n\t"
        "selp.b32 %0, 1, 0, p;\n\t}" : "=r"(done) : "r"(a), "r"(parity) : "memory");
    while (!done) {
        asm volatile("{\n\t.reg .pred p;\n\t"
            "mbarrier.try_wait.parity.acquire.cta.shared::cta.b64 p, [%1], %2, 0x989680;\n\t"
            "selp.b32 %0, 1, 0, p;\n\t}" : "=r"(done) : "r"(a), "r"(parity) : "memory");
    }
}
__device__ __forceinline__ void tma_g2s_pol(unsigned dst, const void* src, unsigned bytes,
                                            unsigned mbar, uint64_t pol) {
    asm volatile(
        "cp.async.bulk.shared::cluster.global.mbarrier::complete_tx::bytes.L2::cache_hint"
        " [%0], [%1], %2, [%3], %4;"
        :: "r"(dst), "l"(src), "r"(bytes), "r"(mbar), "l"(pol) : "memory");
}
__device__ __forceinline__ void fence_pa() {
    asm volatile("fence.proxy.async.shared::cta;" ::: "memory");
}
__device__ __forceinline__ float sigmoidf_(float x) { return 1.f / (1.f + expf(-x)); }

__global__ void init_kernel() {
    int i = blockIdx.x * blockDim.x + threadIdx.x;
    for (; i < 2 * BS * H_; i += gridDim.x * blockDim.x) ((float*)g_h2)[i] = 0.f;
}

// ---- qe = emb @ Wq[:, :512]^T (once) ----
__global__ void __launch_bounds__(256) qe_kernel(const float* __restrict__ emb,
                                                 const float* __restrict__ Wq)
{
    __shared__ float Es[16][68], Qs[16][68];
    int v0 = blockIdx.x * 64, n0 = blockIdx.y * 64;
    int tid = threadIdx.x, tn = tid & 15, tm = tid >> 4;
    float acc[4][4] = {};
    for (int k0 = 0; k0 < 512; k0 += 16) {
        #pragma unroll
        for (int i = 0; i < 4; i++) {
            int e = tid + i * 256, kk = e & 15, mm = e >> 4;
            int v = v0 + mm;
            Es[kk][mm] = (v < V_) ? emb[(size_t)v * H_ + k0 + kk] : 0.f;
            Qs[kk][mm] = Wq[(size_t)(n0 + mm) * (2 * H_) + k0 + kk];
        }
        __syncthreads();
        #pragma unroll
        for (int kk = 0; kk < 16; kk++) {
            float4 xa = *(const float4*)&Es[kk][tm * 4];
            float4 wa = *(const float4*)&Qs[kk][tn * 4];
            float xv[4] = {xa.x, xa.y, xa.z, xa.w};
            float wv[4] = {wa.x, wa.y, wa.z, wa.w};
            #pragma unroll
            for (int i = 0; i < 4; i++)
                #pragma unroll
                for (int j = 0; j < 4; j++)
                    acc[i][j] = fmaf(xv[i], wv[j], acc[i][j]);
        }
        __syncthreads();
    }
    #pragma unroll
    for (int i = 0; i < 4; i++) {
        int v = v0 + tm * 4 + i;
        if (v < V_)
            #pragma unroll
            for (int j = 0; j < 4; j++)
                g_qe[(size_t)v * D_ + n0 + tn * 4 + j] = acc[i][j];
    }
}

// ---- KV projection: f32x2-packed over m-pairs ----
__global__ void __launch_bounds__(256) kvproj_kernel(
    const float* __restrict__ memory, const float* __restrict__ Wk, const float* __restrict__ bk,
    const float* __restrict__ Wv, const float* __restrict__ bv)
{
    __shared__ __align__(16) float Xs[16][132];
    __shared__ __align__(16) float Ks[16][68];
    __shared__ __align__(16) float Vs[16][68];
    const int m0 = blockIdx.x * 128, n0 = blockIdx.y * 64, b = blockIdx.z;
    const int tid = threadIdx.x, tn = tid & 15, tm = tid >> 4;
    uint64_t accK2[4][4] = {}, accV2[4][4] = {};

    for (int k0 = 0; k0 < D_; k0 += 16) {
        #pragma unroll
        for (int i = 0; i < 8; i++) {
            int e = tid + i * 256, kk = e & 15, mm = e >> 4;
            Xs[kk][mm] = memory[((size_t)(m0 + mm) * BS + b) * D_ + k0 + kk];
        }
        #pragma unroll
        for (int i = 0; i < 4; i++) {
            int e = tid + i * 256, kk = e & 15, nn = e >> 4;
            Ks[kk][nn] = Wk[(size_t)(n0 + nn) * D_ + k0 + kk];
            Vs[kk][nn] = Wv[(size_t)(n0 + nn) * D_ + k0 + kk];
        }
        __syncthreads();
        #pragma unroll
        for (int kk = 0; kk < 16; kk++) {
            const ulonglong2* xp = (const ulonglong2*)&Xs[kk][tm * 8];
            ulonglong2 xab = xp[0], xcd = xp[1];
            uint64_t xs2[4] = {xab.x, xab.y, xcd.x, xcd.y};
            float4 kw = *(const float4*)&Ks[kk][tn * 4];
            float4 vw = *(const float4*)&Vs[kk][tn * 4];
            uint64_t kw2[4], vw2[4];
            PACK2(kw2[0], kw.x, kw.x); PACK2(kw2[1], kw.y, kw.y);
            PACK2(kw2[2], kw.z, kw.z); PACK2(kw2[3], kw.w, kw.w);
            PACK2(vw2[0], vw.x, vw.x); PACK2(vw2[1], vw.y, vw.y);
            PACK2(vw2[2], vw.z, vw.z); PACK2(vw2[3], vw.w, vw.w);
            #pragma unroll
            for (int p = 0; p < 4; p++)
                #pragma unroll
                for (int j = 0; j < 4; j++) {
                    FMA2(accK2[p][j], xs2[p], kw2[j]);
                    FMA2(accV2[p][j], xs2[p], vw2[j]);
                }
        }
        __syncthreads();
    }
    #pragma unroll
    for (int j = 0; j < 4; j++) {
        int n = n0 + tn * 4 + j, h = n >> 6, d = n & 63;
        float bkv = bk[n], bvv = bv[n];
        uint64_t bb2; PACK2(bb2, bkv, bkv);
        #pragma unroll
        for (int p = 0; p < 4; p++) {
            int m = m0 + tm * 8 + 2 * p;
            uint64_t kk2; ADD2(kk2, accK2[p][j], bb2);
            *(uint64_t*)&g_kt[(((size_t)b * NH + h) * DK + d) * MEM_ + m] = kk2;
            float vlo, vhi; UNPACK2(vlo, vhi, accV2[p][j]);
            g_vp[(((size_t)b * NH + h) * MEM_ + m)     * DK + d] = vlo + bvv;
            g_vp[(((size_t)b * NH + h) * MEM_ + m + 1) * DK + d] = vhi + bvv;
        }
    }
}

extern __shared__ __align__(128) float dynf[];

__device__ __forceinline__ void grid_bar() {
    __syncthreads();
    if (threadIdx.x == 0) {
        unsigned gen = g_bar_gen;
        __threadfence();
        unsigned ticket = atomicAdd(&g_bar_count, 1u);
        if (ticket == gridDim.x - 1) { g_bar_count = 0; __threadfence(); g_bar_gen = gen + 1; }
        else { while (g_bar_gen == gen) __nanosleep(32); __threadfence(); }
    }
    __syncthreads();
}

__global__ void __launch_bounds__(512, 1) decode_kernel(
    const float* __restrict__ emb,  const float* __restrict__ Wq,  const float* __restrict__ bq,
    const float* __restrict__ Wih,  const float* __restrict__ Whh,
    const float* __restrict__ bih,  const float* __restrict__ bhh,
    const float* __restrict__ Wfc,  const float* __restrict__ bfc,
    const int*   __restrict__ lens, float* __restrict__ out)
{
    const int bid = blockIdx.x, tid = threadIdx.x;
    const int wrp = tid >> 5, lane = tid & 31;
    const int n0q = bid * 4, j0 = bid * 4, n0f = bid * 8;
    const unsigned mb = s2u(&dynf[MBF]);
    const unsigned ring_s = s2u(&dynf[RING]);

    uint64_t l2pol;
    if (bid < NKEEP)
        asm volatile("createpolicy.fractional.L2::evict_last.b64 %0, 1.0;" : "=l"(l2pol));
    else
        asm volatile("createpolicy.fractional.L2::evict_first.b64 %0, 1.0;" : "=l"(l2pol));

    for (int i = tid; i < 4 * 512; i += 512)
        dynf[RWQ + i] = Wq[(size_t)(n0q + (i >> 9)) * (2 * H_) + 512 + (i & 511)];
    for (int i = tid; i < 24 * 512; i += 512) {
        int r24 = i >> 9, k = i & 511, p = r24 / 12, r = r24 % 12, g = r >> 2, jj = r & 3;
        dynf[RWG + i] = (p ? Whh : Wih)[(size_t)(g * H_ + j0 + jj) * H_ + k];
    }
    if (bid < NFC)
        for (int i = tid; i < 8 * 512; i += 512)
            dynf[RWF + i] = Wfc[(size_t)(n0f + (i >> 9)) * H_ + (i & 511)];
    if (tid == 0) { mbar_init(mb, 1u); mbar_init(mb + 8, 1u); mbar_init(mb + 16, 1u); }
    __syncthreads();
    int p0 = 0, p1 = 0, p2 = 0;

    for (int t = 0; t < TMAX; t++) {
        const float* hcur = g_h2[t & 1];
        float* hnext = g_h2[(t + 1) & 1];
        float ghfin[3];

        // ========== Q: toks, q = qe[tok] + Wq_h@h (f32x2), gh = Whh@h (f32x2) ====
        {
            int* TOK = (int*)&dynf[QTOK];
            if (t == 0) { if (tid < BS) TOK[tid] = 0; }
            else {
                float* AV = &dynf[QAV]; int* AI = (int*)&dynf[QAI];
                int l = tid >> 7, b = tid & 127;
                float bv = -3.4e38f; int bi = 0;
                for (int p = l; p < NFC; p += 4) {
                    float v = g_pv[p * BS + b]; int ix = g_pi[p * BS + b];
                    if (v > bv || (v == bv && ix < bi)) { bv = v; bi = ix; }
                }
                AV[l * 128 + b] = bv; AI[l * 128 + b] = bi;
                __syncthreads();
                if (tid < BS) {
                    float cv = AV[tid]; int ci = AI[tid];
                    #pragma unroll
                    for (int l2 = 1; l2 < 4; l2++) {
                        float v = AV[l2 * 128 + tid]; int ix = AI[l2 * 128 + tid];
                        if (v > cv || (v == cv && ix < ci)) { cv = v; ci = ix; }
                    }
                    TOK[tid] = ci;
                }
            }
            __syncthreads();
            const int gb = tid & 127, gjj = tid >> 7;
            uint64_t acc2[4][8] = {};
            uint64_t gh2[3] = {};
            for (int c = 0; c < 4; c++) {
                #pragma unroll
                for (int i = 0; i < 8; i++) {
                    int e = tid + i * 512, b = e >> 5, k4 = e & 31;
                    *(float4*)&dynf[QX + b * 132 + k4 * 4] =
                        *(const float4*)(hcur + b * H_ + c * 128 + k4 * 4);
                }
                __syncthreads();
                #pragma unroll
                for (int j = 0; j < 2; j++) {
                    int kp = lane + 32 * j;     // k-pair index within chunk
                    uint64_t wv2[4];
                    #pragma unroll
                    for (int ni = 0; ni < 4; ni++)
                        wv2[ni] = ((const uint64_t*)&dynf[RWQ + ni * 512 + c * 128])[kp];
                    #pragma unroll
                    for (int bi = 0; bi < 8; bi++) {
                        uint64_t x2 = ((const uint64_t*)&dynf[QX + (wrp * 8 + bi) * 132])[kp];
                        #pragma unroll
                        for (int ni = 0; ni < 4; ni++) FMA2(acc2[ni][bi], x2, wv2[ni]);
                    }
                }
                // gh partials: ulonglong2 = 2 packed k-pairs
                {
                    const ulonglong2* xq = (const ulonglong2*)&dynf[QX + gb * 132];
                    const ulonglong2* w0 = (const ulonglong2*)&dynf[RWG + (12 + gjj) * 512 + c * 128];
                    const ulonglong2* w1 = (const ulonglong2*)&dynf[RWG + (16 + gjj) * 512 + c * 128];
                    const ulonglong2* w2 = (const ulonglong2*)&dynf[RWG + (20 + gjj) * 512 + c * 128];
                    #pragma unroll
                    for (int kq = 0; kq < 32; kq++) {
                        ulonglong2 x2 = xq[kq];
                        ulonglong2 wa = w0[kq], wb = w1[kq], wc = w2[kq];
                        FMA2(gh2[0], x2.x, wa.x); FMA2(gh2[0], x2.y, wa.y);
                        FMA2(gh2[1], x2.x, wb.x); FMA2(gh2[1], x2.y, wb.y);
                        FMA2(gh2[2], x2.x, wc.x); FMA2(gh2[2], x2.y, wc.y);
                    }
                }
                __syncthreads();
            }
            #pragma unroll
            for (int g = 0; g < 3; g++) {
                float lo, hi; UNPACK2(lo, hi, gh2[g]);
                ghfin[g] = lo + hi;
            }
            float accs[4][8];
            #pragma unroll
            for (int ni = 0; ni < 4; ni++)
                #pragma unroll
                for (int bi = 0; bi < 8; bi++) {
                    float lo, hi; UNPACK2(lo, hi, acc2[ni][bi]);
                    accs[ni][bi] = lo + hi;
                }
            #pragma unroll
            for (int j = 0; j < 32; j++) {
                int ni = j >> 3, bi = j & 7;
                float v = accs[ni][bi];
                #pragma unroll
                for (int o = 16; o > 0; o >>= 1) v += __shfl_xor_sync(0xffffffffu, v, o);
                if (lane == j) {
                    int n = n0q + ni, b = wrp * 8 + bi;
                    g_q[b * D_ + n] = v + bq[n] + g_qe[(size_t)((int*)&dynf[QTOK])[b] * D_ + n];
                }
            }
        }
        grid_bar();

        // ========== ATT: unified 64-chunk TMA stream (32 K + 32 V) ==========
        {
            dynf[A_QS + tid] = g_q[bid * D_ + tid];
            __syncthreads();
            const float* ksrc = g_kt + (size_t)bid * NH * DK * MEM_;
            const float* vsrc = g_vp + (size_t)bid * NH * MEM_ * DK;
            if (tid == 0) {
                fence_pa();
                #pragma unroll
                for (int j = 0; j < 3; j++) {
                    mbar_expect_tx(mb + 8u * j, 32768);
                    tma_g2s_pol(ring_s + j * 32768, ksrc + (size_t)j * 8192, 32768, mb + 8u * j, l2pol);
                }
            }
            float acc = 0.f, accv = 0.f;
            const int vg = tid >> 6, vd = tid & 63;
            for (int c = 0; c < 64; c++) {
                int jb = c % 3, pj;
                if (jb == 0) { pj = p0; p0 ^= 1; }
                else if (jb == 1) { pj = p1; p1 ^= 1; }
                else { pj = p2; p2 ^= 1; }
                mbar_wait(mb + 8u * jb, pj);
                const float* Bf = &dynf[RING + jb * 8192];
                if (c < 32) {
                    int h = c >> 2, d0 = (c & 3) * 16;
                    if (d0 == 0) acc = 0.f;
                    #pragma unroll
                    for (int u = 0; u < 16; u++)
                        acc = fmaf(dynf[A_QS + h * DK + d0 + u], Bf[u * MEM_ + tid], acc);
                    if (d0 == 48) dynf[A_SC + h * MEM_ + tid] = acc * 0.125f;
                } else {
                    int cv = c - 32, vh = cv >> 2, m0 = (cv & 3) * 128;
                    if (m0 == 0) accv = 0.f;
                    const float* ph = &dynf[A_SC + vh * MEM_ + m0];
                    #pragma unroll
                    for (int u = 0; u < 16; u++) {
                        int ml = vg * 16 + u;
                        accv = fmaf(ph[ml], Bf[ml * 64 + vd], accv);
                    }
                    if (m0 == 384) dynf[A_RED + (vh * 8 + vg) * 64 + vd] = accv;
                }
                __syncthreads();
                if (c == 31) {
                    int h = tid >> 6, i = tid & 63;
                    float mx = -3.4e38f;
                    #pragma unroll
                    for (int r = 0; r < 8; r++) mx = fmaxf(mx, dynf[A_SC + h * MEM_ + i + (r << 6)]);
                    #pragma unroll
                    for (int o = 16; o > 0; o >>= 1) mx = fmaxf(mx, __shfl_xor_sync(0xffffffffu, mx, o));
                    if ((tid & 31) == 0) dynf[A_W1 + (tid >> 5)] = mx;
                    __syncthreads();
                    float mh = fmaxf(dynf[A_W1 + 2 * h], dynf[A_W1 + 2 * h + 1]);
                    float s = 0.f;
                    #pragma unroll
                    for (int r = 0; r < 8; r++) {
                        int m = i + (r << 6);
                        float e = expf(dynf[A_SC + h * MEM_ + m] - mh);
                        dynf[A_SC + h * MEM_ + m] = e;
                        s += e;
                    }
                    #pragma unroll
                    for (int o = 16; o > 0; o >>= 1) s += __shfl_xor_sync(0xffffffffu, s, o);
                    if ((tid & 31) == 0) dynf[A_W2 + (tid >> 5)] = s;
                    __syncthreads();
                    float inv = 1.f / (dynf[A_W2 + 2 * h] + dynf[A_W2 + 2 * h + 1]);
                    if (i == 0) dynf[A_INV + h] = inv;
                    __syncthreads();
                    float sm = 0.f;
                    #pragma unroll
                    for (int hh = 0; hh < NH; hh++)
                        sm += dynf[A_SC + hh * MEM_ + tid] * dynf[A_INV + hh];
                    sm *= 0.125f;
                    int run = t < lens[bid];
                    out[OUT_S_OFF + ((size_t)t * BS + bid) * MEM_ + tid] = run ? sm : 0.f;
                }
                if (tid == 0 && c + 3 < 64) {
                    int nc = c + 3, j2 = nc % 3;
                    const float* src = (nc < 32) ? (ksrc + (size_t)nc * 8192)
                                                 : (vsrc + (size_t)(nc - 32) * 8192);
                    mbar_expect_tx(mb + 8u * j2, 32768);
                    tma_g2s_pol(ring_s + j2 * 32768, src, 32768, mb + 8u * j2, l2pol);
                }
            }
            int rh = tid >> 6, rd = tid & 63;
            float sum = 0.f;
            #pragma unroll
            for (int gg = 0; gg < 8; gg++) sum += dynf[A_RED + (rh * 8 + gg) * 64 + rd];
            g_ctx[bid * D_ + rh * DK + rd] = sum * dynf[A_INV + rh];
        }
        grid_bar();

        // ========== GRU: gi = Wih@ctx (16-way k-split) + fused activation ======
        {
            const int ks = wrp;
            float ag[12][4] = {};
            for (int c = 0; c < 8; c++) {
                #pragma unroll
                for (int i = 0; i < 8; i++) {
                    int e = tid + i * 512;
                    int r = e >> 5, k2 = e & 31;
                    float2 v = *(const float2*)(g_ctx + r * 512 + c * 64 + k2 * 2);
                    *(float2*)&dynf[GX + r * 64 + ((k2 * 2) ^ ((r & 15) << 1))] = v;
                }
                __syncthreads();
                #pragma unroll
                for (int uu = 0; uu < 4; uu++) {
                    int kk = ks * 4 + uu;
                    int kg = c * 64 + kk;
                    float xv[4];
                    #pragma unroll
                    for (int bi = 0; bi < 4; bi++) {
                        int b = lane + bi * 32;
                        xv[bi] = dynf[GX + b * 64 + (kk ^ ((b & 15) << 1))];
                    }
                    #pragma unroll
                    for (int row = 0; row < 12; row++) {
                        float wv = dynf[RWG + row * 512 + kg];
                        #pragma unroll
                        for (int bi = 0; bi < 4; bi++) ag[row][bi] = fmaf(xv[bi], wv, ag[row][bi]);
                    }
                }
                __syncthreads();
            }
            #pragma unroll
            for (int row = 0; row < 12; row++)
                #pragma unroll
                for (int bi = 0; bi < 4; bi++)
                    dynf[GP + (ks * 12 + row) * 128 + lane + bi * 32] = ag[row][bi];
            __syncthreads();
            {
                int b = tid & 127, jj = tid >> 7, j = j0 + jj;
                float gi[3];
                #pragma unroll
                for (int g = 0; g < 3; g++) {
                    float s0 = 0.f;
                    #pragma unroll
                    for (int k2 = 0; k2 < 16; k2++)
                        s0 += dynf[GP + (k2 * 12 + g * 4 + jj) * 128 + b];
                    gi[g] = s0 + bih[g * H_ + j];
                }
                float ghr = ghfin[0] + bhh[j];
                float ghz = ghfin[1] + bhh[H_ + j];
                float ghn = ghfin[2] + bhh[2 * H_ + j];
                float rr = sigmoidf_(gi[0] + ghr);
                float zz = sigmoidf_(gi[1] + ghz);
                float nn = tanhf(gi[2] + rr * ghn);
                float hold = hcur[b * H_ + j];
                float hn = (1.f - zz) * nn + zz * hold;
                hnext[b * H_ + j] = hn;
                int run = t < lens[b];
                out[OUT_H_OFF + ((size_t)t * BS + b) * H_ + j] = run ? hn : 0.f;
            }
        }
        grid_bar();

        // ========== FC + partial argmax ==========
        if (bid < NFC) {
            float af[8][8] = {};
            for (int c = 0; c < 4; c++) {
                #pragma unroll
                for (int i = 0; i < 8; i++) {
                    int e = tid + i * 512, b = e >> 5, k4 = e & 31;
                    *(float4*)&dynf[FX + b * 132 + k4 * 4] =
                        *(const float4*)(hnext + b * H_ + c * 128 + k4 * 4);
                }
                __syncthreads();
                #pragma unroll
                for (int j = 0; j < 4; j++) {
                    int kk = lane + 32 * j;
                    float wv[8];
                    #pragma unroll
                    for (int ni = 0; ni < 8; ni++) wv[ni] = dynf[RWF + ni * 512 + c * 128 + kk];
                    #pragma unroll
                    for (int bi = 0; bi < 8; bi++) {
                        float x = dynf[FX + (wrp * 8 + bi) * 132 + kk];
                        #pragma unroll
                        for (int ni = 0; ni < 8; ni++) af[ni][bi] = fmaf(x, wv[ni], af[ni][bi]);
                    }
                }
                __syncthreads();
            }
            float rr0 = 0.f, rr1 = 0.f;
            #pragma unroll
            for (int j = 0; j < 64; j++) {
                int ni = j >> 3, bi = j & 7;
                float v = af[ni][bi];
                #pragma unroll
                for (int o = 16; o > 0; o >>= 1) v += __shfl_xor_sync(0xffffffffu, v, o);
                if (lane == (j & 31)) { if (j < 32) rr0 = v; else rr1 = v; }
            }
            int bi = lane & 7, b = wrp * 8 + bi;
            int nA = n0f + (lane >> 3), nB = nA + 4;
            float vA = rr0 + bfc[nA], vB = rr1 + bfc[nB];
            int run = t < lens[b];
            size_t ob = ((size_t)t * BS + b) * V_;
            out[ob + nA] = run ? vA : 0.f;
            out[ob + nB] = run ? vB : 0.f;
            float mv = vA; int mi = nA;
            if (vB > mv) { mv = vB; mi = nB; }
            #pragma unroll
            for (int o = 8; o <= 16; o <<= 1) {
                float v2 = __shfl_xor_sync(0xffffffffu, mv, o);
                int   i2 = __shfl_xor_sync(0xffffffffu, mi, o);
                if (v2 > mv || (v2 == mv && i2 < mi)) { mv = v2; mi = i2; }
            }
            if (lane < 8) { g_pv[bid * BS + b] = mv; g_pi[bid * BS + b] = mi; }
        }
        grid_bar();
    }
}

extern "C" void kernel_launch(void* const* d_in, const int* in_sizes, int n_in,
                              void* d_out, int out_size)
{
    const float* memory = (const float*)d_in[0];
    const float* emb    = (const float*)d_in[1];
    const float* Wq     = (const float*)d_in[2];
    const float* bq     = (const float*)d_in[3];
    const float* Wk     = (const float*)d_in[4];
    const float* bk     = (const float*)d_in[5];
    const float* Wv     = (const float*)d_in[6];
    const float* bv     = (const float*)d_in[7];
    const float* Wih    = (const float*)d_in[8];
    const float* Whh    = (const float*)d_in[9];
    const float* bih    = (const float*)d_in[10];
    const float* bhh    = (const float*)d_in[11];
    const float* Wfc    = (const float*)d_in[12];
    const float* bfc    = (const float*)d_in[13];
    const int*   lens   = (const int*)d_in[14];
    float* out = (float*)d_out;

    cudaFuncSetAttribute(decode_kernel, cudaFuncAttributeMaxDynamicSharedMemorySize, SMEM_BYTES);

    init_kernel<<<128, 256>>>();
    qe_kernel<<<dim3(16, 8), 256>>>(emb, Wq);
    kvproj_kernel<<<dim3(MEM_ / 128, D_ / 64, BS), 256>>>(memory, Wk, bk, Wv, bv);
    decode_kernel<<<NBLK, 512, SMEM_BYTES>>>(emb, Wq, bq, Wih, Whh, bih, bhh, Wfc, bfc, lens, out);
}

// round 17
// speedup vs baseline: 2.1496x; 1.0952x over previous
#include <cuda_runtime.h>
#include <math.h>
#include <stdint.h>

#define V_   1000
#define H_   512
#define D_   512
#define NH   8
#define DK   64
#define MEM_ 512
#define BS   128
#define TMAX 160
#define NBLK 128
#define NFC  125
#define NKEEP 50

#define OUT_H_OFF (TMAX*BS*V_)
#define OUT_S_OFF (OUT_H_OFF + TMAX*BS*H_)

// ---- dynamic smem layout (float indices) ----
#define A_QS   0
#define A_SC   512
#define A_RED  4608
#define A_W1   8704
#define A_W2   8720
#define A_INV  8736
#define RING   8768
#define QX     0
#define QTOK   16896
#define QAV    17024
#define QAI    17536
#define GX     0
#define GP     0
#define FX     0
#define RWQ    33376
#define RWG    37472
#define RWF    49760
#define MBF    53856
#define SMEM_BYTES (53864*4)

__device__ __align__(256) float g_kt[(size_t)BS*NH*DK*MEM_];
__device__ __align__(256) float g_vp[(size_t)BS*NH*MEM_*DK];
__device__ float g_qe[(size_t)V_*D_];
__device__ float g_h2[2][BS*H_];
__device__ float g_q [BS*D_];
__device__ float g_ctx[BS*D_];
__device__ float g_pv[NFC*BS];
__device__ int   g_pi[NFC*BS];
__device__ unsigned g_bar_count;
__device__ volatile unsigned g_bar_gen;

// ---- f32x2 packed math ----
#define FMA2(d, a, b) asm("fma.rn.f32x2 %0, %1, %2, %0;" : "+l"(d) : "l"(a), "l"(b))
#define ADD2(d, a, b) asm("add.rn.f32x2 %0, %1, %2;" : "=l"(d) : "l"(a), "l"(b))
#define PACK2(d, lo, hi) asm("mov.b64 %0, {%1, %2};" : "=l"(d) \
    : "r"(__float_as_uint(lo)), "r"(__float_as_uint(hi)))
#define UNPACK2(lo, hi, s) do { unsigned _ulo, _uhi; \
    asm("mov.b64 {%0, %1}, %2;" : "=r"(_ulo), "=r"(_uhi) : "l"(s)); \
    lo = __uint_as_float(_ulo); hi = __uint_as_float(_uhi); } while (0)

__device__ __forceinline__ unsigned s2u(const void* p) {
    return (unsigned)__cvta_generic_to_shared(p);
}
__device__ __forceinline__ void mbar_init(unsigned a, unsigned cnt) {
    asm volatile("mbarrier.init.shared.b64 [%0], %1;" :: "r"(a), "r"(cnt) : "memory");
}
__device__ __forceinline__ void mbar_expect_tx(unsigned a, unsigned bytes) {
    asm volatile("mbarrier.arrive.expect_tx.shared.b64 _, [%0], %1;" :: "r"(a), "r"(bytes) : "memory");
}
__device__ __forceinline__ void mbar_wait(unsigned a, unsigned parity) {
    unsigned done;
    asm volatile("{\n\t.reg .pred p;\n\t"
        "mbarrier.try_wait.parity.acquire.cta.shared::cta.b64 p, [%1], %2, 0x989680;\n\t"
        "selp.b32 %0, 1, 0, p;\n\t}" : "=r"(done) : "r"(a), "r"(parity) : "memory");
    while (!done) {
        asm volatile("{\n\t.reg .pred p;\n\t"
            "mbarrier.try_wait.parity.acquire.cta.shared::cta.b64 p, [%1], %2, 0x989680;\n\t"
            "selp.b32 %0, 1, 0, p;\n\t}" : "=r"(done) : "r"(a), "r"(parity) : "memory");
    }
}
__device__ __forceinline__ void tma_g2s_pol(unsigned dst, const void* src, unsigned bytes,
                                            unsigned mbar, uint64_t pol) {
    asm volatile(
        "cp.async.bulk.shared::cluster.global.mbarrier::complete_tx::bytes.L2::cache_hint"
        " [%0], [%1], %2, [%3], %4;"
        :: "r"(dst), "l"(src), "r"(bytes), "r"(mbar), "l"(pol) : "memory");
}
__device__ __forceinline__ void fence_pa() {
    asm volatile("fence.proxy.async.shared::cta;" ::: "memory");
}
__device__ __forceinline__ float sigmoidf_(float x) { return 1.f / (1.f + expf(-x)); }

__global__ void init_kernel() {
    int i = blockIdx.x * blockDim.x + threadIdx.x;
    for (; i < 2 * BS * H_; i += gridDim.x * blockDim.x) ((float*)g_h2)[i] = 0.f;
}

// ---- qe = emb @ Wq[:, :512]^T (once) ----
__global__ void __launch_bounds__(256) qe_kernel(const float* __restrict__ emb,
                                                 const float* __restrict__ Wq)
{
    __shared__ float Es[16][68], Qs[16][68];
    int v0 = blockIdx.x * 64, n0 = blockIdx.y * 64;
    int tid = threadIdx.x, tn = tid & 15, tm = tid >> 4;
    float acc[4][4] = {};
    for (int k0 = 0; k0 < 512; k0 += 16) {
        #pragma unroll
        for (int i = 0; i < 4; i++) {
            int e = tid + i * 256, kk = e & 15, mm = e >> 4;
            int v = v0 + mm;
            Es[kk][mm] = (v < V_) ? emb[(size_t)v * H_ + k0 + kk] : 0.f;
            Qs[kk][mm] = Wq[(size_t)(n0 + mm) * (2 * H_) + k0 + kk];
        }
        __syncthreads();
        #pragma unroll
        for (int kk = 0; kk < 16; kk++) {
            float4 xa = *(const float4*)&Es[kk][tm * 4];
            float4 wa = *(const float4*)&Qs[kk][tn * 4];
            float xv[4] = {xa.x, xa.y, xa.z, xa.w};
            float wv[4] = {wa.x, wa.y, wa.z, wa.w};
            #pragma unroll
            for (int i = 0; i < 4; i++)
                #pragma unroll
                for (int j = 0; j < 4; j++)
                    acc[i][j] = fmaf(xv[i], wv[j], acc[i][j]);
        }
        __syncthreads();
    }
    #pragma unroll
    for (int i = 0; i < 4; i++) {
        int v = v0 + tm * 4 + i;
        if (v < V_)
            #pragma unroll
            for (int j = 0; j < 4; j++)
                g_qe[(size_t)v * D_ + n0 + tn * 4 + j] = acc[i][j];
    }
}

// ---- KV projection: f32x2-packed over m-pairs ----
__global__ void __launch_bounds__(256) kvproj_kernel(
    const float* __restrict__ memory, const float* __restrict__ Wk, const float* __restrict__ bk,
    const float* __restrict__ Wv, const float* __restrict__ bv)
{
    __shared__ __align__(16) float Xs[16][132];
    __shared__ __align__(16) float Ks[16][68];
    __shared__ __align__(16) float Vs[16][68];
    const int m0 = blockIdx.x * 128, n0 = blockIdx.y * 64, b = blockIdx.z;
    const int tid = threadIdx.x, tn = tid & 15, tm = tid >> 4;
    uint64_t accK2[4][4] = {}, accV2[4][4] = {};

    for (int k0 = 0; k0 < D_; k0 += 16) {
        #pragma unroll
        for (int i = 0; i < 8; i++) {
            int e = tid + i * 256, kk = e & 15, mm = e >> 4;
            Xs[kk][mm] = memory[((size_t)(m0 + mm) * BS + b) * D_ + k0 + kk];
        }
        #pragma unroll
        for (int i = 0; i < 4; i++) {
            int e = tid + i * 256, kk = e & 15, nn = e >> 4;
            Ks[kk][nn] = Wk[(size_t)(n0 + nn) * D_ + k0 + kk];
            Vs[kk][nn] = Wv[(size_t)(n0 + nn) * D_ + k0 + kk];
        }
        __syncthreads();
        #pragma unroll
        for (int kk = 0; kk < 16; kk++) {
            const ulonglong2* xp = (const ulonglong2*)&Xs[kk][tm * 8];
            ulonglong2 xab = xp[0], xcd = xp[1];
            uint64_t xs2[4] = {xab.x, xab.y, xcd.x, xcd.y};
            float4 kw = *(const float4*)&Ks[kk][tn * 4];
            float4 vw = *(const float4*)&Vs[kk][tn * 4];
            uint64_t kw2[4], vw2[4];
            PACK2(kw2[0], kw.x, kw.x); PACK2(kw2[1], kw.y, kw.y);
            PACK2(kw2[2], kw.z, kw.z); PACK2(kw2[3], kw.w, kw.w);
            PACK2(vw2[0], vw.x, vw.x); PACK2(vw2[1], vw.y, vw.y);
            PACK2(vw2[2], vw.z, vw.z); PACK2(vw2[3], vw.w, vw.w);
            #pragma unroll
            for (int p = 0; p < 4; p++)
                #pragma unroll
                for (int j = 0; j < 4; j++) {
                    FMA2(accK2[p][j], xs2[p], kw2[j]);
                    FMA2(accV2[p][j], xs2[p], vw2[j]);
                }
        }
        __syncthreads();
    }
    #pragma unroll
    for (int j = 0; j < 4; j++) {
        int n = n0 + tn * 4 + j, h = n >> 6, d = n & 63;
        float bkv = bk[n], bvv = bv[n];
        uint64_t bb2; PACK2(bb2, bkv, bkv);
        #pragma unroll
        for (int p = 0; p < 4; p++) {
            int m = m0 + tm * 8 + 2 * p;
            uint64_t kk2; ADD2(kk2, accK2[p][j], bb2);
            *(uint64_t*)&g_kt[(((size_t)b * NH + h) * DK + d) * MEM_ + m] = kk2;
            float vlo, vhi; UNPACK2(vlo, vhi, accV2[p][j]);
            g_vp[(((size_t)b * NH + h) * MEM_ + m)     * DK + d] = vlo + bvv;
            g_vp[(((size_t)b * NH + h) * MEM_ + m + 1) * DK + d] = vhi + bvv;
        }
    }
}

extern __shared__ __align__(128) float dynf[];

__device__ __forceinline__ void grid_bar() {
    __syncthreads();
    if (threadIdx.x == 0) {
        unsigned gen = g_bar_gen;
        __threadfence();
        unsigned ticket = atomicAdd(&g_bar_count, 1u);
        if (ticket == gridDim.x - 1) { g_bar_count = 0; __threadfence(); g_bar_gen = gen + 1; }
        else { while (g_bar_gen == gen) __nanosleep(32); __threadfence(); }
    }
    __syncthreads();
}

__global__ void __launch_bounds__(512, 1) decode_kernel(
    const float* __restrict__ emb,  const float* __restrict__ Wq,  const float* __restrict__ bq,
    const float* __restrict__ Wih,  const float* __restrict__ Whh,
    const float* __restrict__ bih,  const float* __restrict__ bhh,
    const float* __restrict__ Wfc,  const float* __restrict__ bfc,
    const int*   __restrict__ lens, float* __restrict__ out)
{
    const int bid = blockIdx.x, tid = threadIdx.x;
    const int wrp = tid >> 5, lane = tid & 31;
    const int n0q = bid * 4, j0 = bid * 4, n0f = bid * 8;
    const unsigned mb = s2u(&dynf[MBF]);
    const unsigned ring_s = s2u(&dynf[RING]);

    uint64_t l2pol;
    if (bid < NKEEP)
        asm volatile("createpolicy.fractional.L2::evict_last.b64 %0, 1.0;" : "=l"(l2pol));
    else
        asm volatile("createpolicy.fractional.L2::evict_first.b64 %0, 1.0;" : "=l"(l2pol));

    for (int i = tid; i < 4 * 512; i += 512)
        dynf[RWQ + i] = Wq[(size_t)(n0q + (i >> 9)) * (2 * H_) + 512 + (i & 511)];
    for (int i = tid; i < 24 * 512; i += 512) {
        int r24 = i >> 9, k = i & 511, p = r24 / 12, r = r24 % 12, g = r >> 2, jj = r & 3;
        dynf[RWG + i] = (p ? Whh : Wih)[(size_t)(g * H_ + j0 + jj) * H_ + k];
    }
    if (bid < NFC)
        for (int i = tid; i < 8 * 512; i += 512)
            dynf[RWF + i] = Wfc[(size_t)(n0f + (i >> 9)) * H_ + (i & 511)];
    if (tid == 0) { mbar_init(mb, 1u); mbar_init(mb + 8, 1u); mbar_init(mb + 16, 1u); }
    __syncthreads();
    int p0 = 0, p1 = 0, p2 = 0;
    const int mylen = lens[bid];

    for (int t = 0; t < TMAX; t++) {
        const float* hcur = g_h2[t & 1];
        float* hnext = g_h2[(t + 1) & 1];
        float ghfin[3];

        // ========== Q: toks, q = qe[tok] + Wq_h@h (f32x2), gh = Whh@h (f32x2) ====
        {
            int* TOK = (int*)&dynf[QTOK];
            if (t == 0) { if (tid < BS) TOK[tid] = 0; }
            else {
                float* AV = &dynf[QAV]; int* AI = (int*)&dynf[QAI];
                int l = tid >> 7, b = tid & 127;
                float bv = -3.4e38f; int bi = 0;
                for (int p = l; p < NFC; p += 4) {
                    float v = g_pv[p * BS + b]; int ix = g_pi[p * BS + b];
                    if (v > bv || (v == bv && ix < bi)) { bv = v; bi = ix; }
                }
                AV[l * 128 + b] = bv; AI[l * 128 + b] = bi;
                __syncthreads();
                if (tid < BS) {
                    float cv = AV[tid]; int ci = AI[tid];
                    #pragma unroll
                    for (int l2 = 1; l2 < 4; l2++) {
                        float v = AV[l2 * 128 + tid]; int ix = AI[l2 * 128 + tid];
                        if (v > cv || (v == cv && ix < ci)) { cv = v; ci = ix; }
                    }
                    TOK[tid] = ci;
                }
            }
            __syncthreads();
            const int gb = tid & 127, gjj = tid >> 7;
            uint64_t acc2[4][8] = {};
            uint64_t gh2[3] = {};
            for (int c = 0; c < 4; c++) {
                #pragma unroll
                for (int i = 0; i < 8; i++) {
                    int e = tid + i * 512, b = e >> 5, k4 = e & 31;
                    *(float4*)&dynf[QX + b * 132 + k4 * 4] =
                        *(const float4*)(hcur + b * H_ + c * 128 + k4 * 4);
                }
                __syncthreads();
                #pragma unroll
                for (int j = 0; j < 2; j++) {
                    int kp = lane + 32 * j;
                    uint64_t wv2[4];
                    #pragma unroll
                    for (int ni = 0; ni < 4; ni++)
                        wv2[ni] = ((const uint64_t*)&dynf[RWQ + ni * 512 + c * 128])[kp];
                    #pragma unroll
                    for (int bi = 0; bi < 8; bi++) {
                        uint64_t x2 = ((const uint64_t*)&dynf[QX + (wrp * 8 + bi) * 132])[kp];
                        #pragma unroll
                        for (int ni = 0; ni < 4; ni++) FMA2(acc2[ni][bi], x2, wv2[ni]);
                    }
                }
                {
                    const ulonglong2* xq = (const ulonglong2*)&dynf[QX + gb * 132];
                    const ulonglong2* w0 = (const ulonglong2*)&dynf[RWG + (12 + gjj) * 512 + c * 128];
                    const ulonglong2* w1 = (const ulonglong2*)&dynf[RWG + (16 + gjj) * 512 + c * 128];
                    const ulonglong2* w2 = (const ulonglong2*)&dynf[RWG + (20 + gjj) * 512 + c * 128];
                    #pragma unroll
                    for (int kq = 0; kq < 32; kq++) {
                        ulonglong2 x2 = xq[kq];
                        ulonglong2 wa = w0[kq], wb = w1[kq], wc = w2[kq];
                        FMA2(gh2[0], x2.x, wa.x); FMA2(gh2[0], x2.y, wa.y);
                        FMA2(gh2[1], x2.x, wb.x); FMA2(gh2[1], x2.y, wb.y);
                        FMA2(gh2[2], x2.x, wc.x); FMA2(gh2[2], x2.y, wc.y);
                    }
                }
                __syncthreads();
            }
            #pragma unroll
            for (int g = 0; g < 3; g++) {
                float lo, hi; UNPACK2(lo, hi, gh2[g]);
                ghfin[g] = lo + hi;
            }
            float accs[4][8];
            #pragma unroll
            for (int ni = 0; ni < 4; ni++)
                #pragma unroll
                for (int bi = 0; bi < 8; bi++) {
                    float lo, hi; UNPACK2(lo, hi, acc2[ni][bi]);
                    accs[ni][bi] = lo + hi;
                }
            #pragma unroll
            for (int j = 0; j < 32; j++) {
                int ni = j >> 3, bi = j & 7;
                float v = accs[ni][bi];
                #pragma unroll
                for (int o = 16; o > 0; o >>= 1) v += __shfl_xor_sync(0xffffffffu, v, o);
                if (lane == j) {
                    int n = n0q + ni, b = wrp * 8 + bi;
                    g_q[b * D_ + n] = v + bq[n] + g_qe[(size_t)((int*)&dynf[QTOK])[b] * D_ + n];
                }
            }
        }
        grid_bar();

        // ========== ATT: skipped entirely for finished batch items ==========
        if (t < mylen) {
            dynf[A_QS + tid] = g_q[bid * D_ + tid];
            __syncthreads();
            const float* ksrc = g_kt + (size_t)bid * NH * DK * MEM_;
            const float* vsrc = g_vp + (size_t)bid * NH * MEM_ * DK;
            if (tid == 0) {
                fence_pa();
                #pragma unroll
                for (int j = 0; j < 3; j++) {
                    mbar_expect_tx(mb + 8u * j, 32768);
                    tma_g2s_pol(ring_s + j * 32768, ksrc + (size_t)j * 8192, 32768, mb + 8u * j, l2pol);
                }
            }
            float acc = 0.f, accv = 0.f;
            const int vg = tid >> 6, vd = tid & 63;
            for (int c = 0; c < 64; c++) {
                int jb = c % 3, pj;
                if (jb == 0) { pj = p0; p0 ^= 1; }
                else if (jb == 1) { pj = p1; p1 ^= 1; }
                else { pj = p2; p2 ^= 1; }
                mbar_wait(mb + 8u * jb, pj);
                const float* Bf = &dynf[RING + jb * 8192];
                if (c < 32) {
                    int h = c >> 2, d0 = (c & 3) * 16;
                    if (d0 == 0) acc = 0.f;
                    #pragma unroll
                    for (int u = 0; u < 16; u++)
                        acc = fmaf(dynf[A_QS + h * DK + d0 + u], Bf[u * MEM_ + tid], acc);
                    if (d0 == 48) dynf[A_SC + h * MEM_ + tid] = acc * 0.125f;
                } else {
                    int cv = c - 32, vh = cv >> 2, m0 = (cv & 3) * 128;
                    if (m0 == 0) accv = 0.f;
                    const float* ph = &dynf[A_SC + vh * MEM_ + m0];
                    #pragma unroll
                    for (int u = 0; u < 16; u++) {
                        int ml = vg * 16 + u;
                        accv = fmaf(ph[ml], Bf[ml * 64 + vd], accv);
                    }
                    if (m0 == 384) dynf[A_RED + (vh * 8 + vg) * 64 + vd] = accv;
                }
                __syncthreads();
                if (c == 31) {
                    int h = tid >> 6, i = tid & 63;
                    float mx = -3.4e38f;
                    #pragma unroll
                    for (int r = 0; r < 8; r++) mx = fmaxf(mx, dynf[A_SC + h * MEM_ + i + (r << 6)]);
                    #pragma unroll
                    for (int o = 16; o > 0; o >>= 1) mx = fmaxf(mx, __shfl_xor_sync(0xffffffffu, mx, o));
                    if ((tid & 31) == 0) dynf[A_W1 + (tid >> 5)] = mx;
                    __syncthreads();
                    float mh = fmaxf(dynf[A_W1 + 2 * h], dynf[A_W1 + 2 * h + 1]);
                    float s = 0.f;
                    #pragma unroll
                    for (int r = 0; r < 8; r++) {
                        int m = i + (r << 6);
                        float e = expf(dynf[A_SC + h * MEM_ + m] - mh);
                        dynf[A_SC + h * MEM_ + m] = e;
                        s += e;
                    }
                    #pragma unroll
                    for (int o = 16; o > 0; o >>= 1) s += __shfl_xor_sync(0xffffffffu, s, o);
                    if ((tid & 31) == 0) dynf[A_W2 + (tid >> 5)] = s;
                    __syncthreads();
                    float inv = 1.f / (dynf[A_W2 + 2 * h] + dynf[A_W2 + 2 * h + 1]);
                    if (i == 0) dynf[A_INV + h] = inv;
                    __syncthreads();
                    float sm = 0.f;
                    #pragma unroll
                    for (int hh = 0; hh < NH; hh++)
                        sm += dynf[A_SC + hh * MEM_ + tid] * dynf[A_INV + hh];
                    sm *= 0.125f;
                    out[OUT_S_OFF + ((size_t)t * BS + bid) * MEM_ + tid] = sm;
                }
                if (tid == 0 && c + 3 < 64) {
                    int nc = c + 3, j2 = nc % 3;
                    const float* src = (nc < 32) ? (ksrc + (size_t)nc * 8192)
                                                 : (vsrc + (size_t)(nc - 32) * 8192);
                    mbar_expect_tx(mb + 8u * j2, 32768);
                    tma_g2s_pol(ring_s + j2 * 32768, src, 32768, mb + 8u * j2, l2pol);
                }
            }
            int rh = tid >> 6, rd = tid & 63;
            float sum = 0.f;
            #pragma unroll
            for (int gg = 0; gg < 8; gg++) sum += dynf[A_RED + (rh * 8 + gg) * 64 + rd];
            g_ctx[bid * D_ + rh * DK + rd] = sum * dynf[A_INV + rh];
        } else {
            // finished item: only the mandated zero scores output
            out[OUT_S_OFF + ((size_t)t * BS + bid) * MEM_ + tid] = 0.f;
        }
        grid_bar();

        // ========== GRU: gi = Wih@ctx (16-way k-split) + fused activation ======
        {
            const int ks = wrp;
            float ag[12][4] = {};
            for (int c = 0; c < 8; c++) {
                #pragma unroll
                for (int i = 0; i < 8; i++) {
                    int e = tid + i * 512;
                    int r = e >> 5, k2 = e & 31;
                    float2 v = *(const float2*)(g_ctx + r * 512 + c * 64 + k2 * 2);
                    *(float2*)&dynf[GX + r * 64 + ((k2 * 2) ^ ((r & 15) << 1))] = v;
                }
                __syncthreads();
                #pragma unroll
                for (int uu = 0; uu < 4; uu++) {
                    int kk = ks * 4 + uu;
                    int kg = c * 64 + kk;
                    float xv[4];
                    #pragma unroll
                    for (int bi = 0; bi < 4; bi++) {
                        int b = lane + bi * 32;
                        xv[bi] = dynf[GX + b * 64 + (kk ^ ((b & 15) << 1))];
                    }
                    #pragma unroll
                    for (int row = 0; row < 12; row++) {
                        float wv = dynf[RWG + row * 512 + kg];
                        #pragma unroll
                        for (int bi = 0; bi < 4; bi++) ag[row][bi] = fmaf(xv[bi], wv, ag[row][bi]);
                    }
                }
                __syncthreads();
            }
            #pragma unroll
            for (int row = 0; row < 12; row++)
                #pragma unroll
                for (int bi = 0; bi < 4; bi++)
                    dynf[GP + (ks * 12 + row) * 128 + lane + bi * 32] = ag[row][bi];
            __syncthreads();
            {
                int b = tid & 127, jj = tid >> 7, j = j0 + jj;
                float gi[3];
                #pragma unroll
                for (int g = 0; g < 3; g++) {
                    float s0 = 0.f;
                    #pragma unroll
                    for (int k2 = 0; k2 < 16; k2++)
                        s0 += dynf[GP + (k2 * 12 + g * 4 + jj) * 128 + b];
                    gi[g] = s0 + bih[g * H_ + j];
                }
                float ghr = ghfin[0] + bhh[j];
                float ghz = ghfin[1] + bhh[H_ + j];
                float ghn = ghfin[2] + bhh[2 * H_ + j];
                float rr = sigmoidf_(gi[0] + ghr);
                float zz = sigmoidf_(gi[1] + ghz);
                float nn = tanhf(gi[2] + rr * ghn);
                float hold = hcur[b * H_ + j];
                float hn = (1.f - zz) * nn + zz * hold;
                hnext[b * H_ + j] = hn;
                int run = t < lens[b];
                out[OUT_H_OFF + ((size_t)t * BS + b) * H_ + j] = run ? hn : 0.f;
            }
        }
        grid_bar();

        // ========== FC + partial argmax ==========
        if (bid < NFC) {
            float af[8][8] = {};
            for (int c = 0; c < 4; c++) {
                #pragma unroll
                for (int i = 0; i < 8; i++) {
                    int e = tid + i * 512, b = e >> 5, k4 = e & 31;
                    *(float4*)&dynf[FX + b * 132 + k4 * 4] =
                        *(const float4*)(hnext + b * H_ + c * 128 + k4 * 4);
                }
                __syncthreads();
                #pragma unroll
                for (int j = 0; j < 4; j++) {
                    int kk = lane + 32 * j;
                    float wv[8];
                    #pragma unroll
                    for (int ni = 0; ni < 8; ni++) wv[ni] = dynf[RWF + ni * 512 + c * 128 + kk];
                    #pragma unroll
                    for (int bi = 0; bi < 8; bi++) {
                        float x = dynf[FX + (wrp * 8 + bi) * 132 + kk];
                        #pragma unroll
                        for (int ni = 0; ni < 8; ni++) af[ni][bi] = fmaf(x, wv[ni], af[ni][bi]);
                    }
                }
                __syncthreads();
            }
            float rr0 = 0.f, rr1 = 0.f;
            #pragma unroll
            for (int j = 0; j < 64; j++) {
                int ni = j >> 3, bi = j & 7;
                float v = af[ni][bi];
                #pragma unroll
                for (int o = 16; o > 0; o >>= 1) v += __shfl_xor_sync(0xffffffffu, v, o);
                if (lane == (j & 31)) { if (j < 32) rr0 = v; else rr1 = v; }
            }
            int bi = lane & 7, b = wrp * 8 + bi;
            int nA = n0f + (lane >> 3), nB = nA + 4;
            float vA = rr0 + bfc[nA], vB = rr1 + bfc[nB];
            int run = t < lens[b];
            size_t ob = ((size_t)t * BS + b) * V_;
            out[ob + nA] = run ? vA : 0.f;
            out[ob + nB] = run ? vB : 0.f;
            float mv = vA; int mi = nA;
            if (vB > mv) { mv = vB; mi = nB; }
            #pragma unroll
            for (int o = 8; o <= 16; o <<= 1) {
                float v2 = __shfl_xor_sync(0xffffffffu, mv, o);
                int   i2 = __shfl_xor_sync(0xffffffffu, mi, o);
                if (v2 > mv || (v2 == mv && i2 < mi)) { mv = v2; mi = i2; }
            }
            if (lane < 8) { g_pv[bid * BS + b] = mv; g_pi[bid * BS + b] = mi; }
        }
        grid_bar();
    }
}

extern "C" void kernel_launch(void* const* d_in, const int* in_sizes, int n_in,
                              void* d_out, int out_size)
{
    const float* memory = (const float*)d_in[0];
    const float* emb    = (const float*)d_in[1];
    const float* Wq     = (const float*)d_in[2];
    const float* bq     = (const float*)d_in[3];
    const float* Wk     = (const float*)d_in[4];
    const float* bk     = (const float*)d_in[5];
    const float* Wv     = (const float*)d_in[6];
    const float* bv     = (const float*)d_in[7];
    const float* Wih    = (const float*)d_in[8];
    const float* Whh    = (const float*)d_in[9];
    const float* bih    = (const float*)d_in[10];
    const float* bhh    = (const float*)d_in[11];
    const float* Wfc    = (const float*)d_in[12];
    const float* bfc    = (const float*)d_in[13];
    const int*   lens   = (const int*)d_in[14];
    float* out = (float*)d_out;

    cudaFuncSetAttribute(decode_kernel, cudaFuncAttributeMaxDynamicSharedMemorySize, SMEM_BYTES);

    init_kernel<<<128, 256>>>();
    qe_kernel<<<dim3(16, 8), 256>>>(emb, Wq);
    kvproj_kernel<<<dim3(MEM_ / 128, D_ / 64, BS), 256>>>(memory, Wk, bk, Wv, bv);
    decode_kernel<<<NBLK, 512, SMEM_BYTES>>>(emb, Wq, bq, Wih, Whh, bih, bhh, Wfc, bfc, lens, out);
}